// round 1
// baseline (speedup 1.0000x reference)
#include <cuda_runtime.h>
#include <math.h>

// Problem constants
#define D_MODEL 768
#define N_HEADS 12
#define D_FF    3072
#define D_KH    64
#define BATCH   2
#define SEQ     2048
#define ROWS    (BATCH * SEQ)                 // 4096
#define OUT_ELEMS ((size_t)ROWS * D_MODEL)    // 3,145,728
#define ATTN_ELEMS ((size_t)BATCH * N_HEADS * SEQ * SEQ)

// Scratch (no cudaMalloc allowed)
__device__ float g_q[ROWS * D_MODEL];
__device__ float g_k[ROWS * D_MODEL];
__device__ float g_v[ROWS * D_MODEL];
__device__ float g_ctx[ROWS * D_MODEL];
__device__ float g_t1[ROWS * D_MODEL];
__device__ float g_ao[ROWS * D_MODEL];
__device__ float g_ffn[ROWS * D_FF];
__device__ float g_t2[ROWS * D_MODEL];

// ---------------------------------------------------------------------------
// Generic NN GEMM: C[M,N] = A[M,K] @ B[K,N] + bias, optional ReLU.
// All dims divisible by tile sizes in every call site (asserted by construction).
// ---------------------------------------------------------------------------
template <int BM, int BN, int BK, int TM, int TN, bool RELU>
__global__ void __launch_bounds__(256)
gemm_bias_kernel(const float* __restrict__ A, int lda,
                 const float* __restrict__ B, int ldb,
                 float* __restrict__ C, int ldc,
                 const float* __restrict__ bias, int K)
{
    constexpr int THREADS = (BM / TM) * (BN / TN);
    static_assert(THREADS == 256, "tile config must use 256 threads");
    __shared__ float As[BK][BM];
    __shared__ float Bs[BK][BN];

    const int tid  = threadIdx.x;
    const int tcol = tid % (BN / TN);
    const int trow = tid / (BN / TN);
    const int row0 = blockIdx.y * BM;
    const int col0 = blockIdx.x * BN;

    A += (size_t)row0 * lda;
    B += col0;

    float acc[TM][TN];
#pragma unroll
    for (int i = 0; i < TM; i++)
#pragma unroll
        for (int j = 0; j < TN; j++) acc[i][j] = 0.f;

    for (int kt = 0; kt < K; kt += BK) {
        // Load A tile [BM x BK], store transposed As[k][m]
#pragma unroll
        for (int l = 0; l < BM * BK / (THREADS * 4); l++) {
            int idx = tid + l * THREADS;
            int ar = idx / (BK / 4);
            int ac = idx % (BK / 4);
            float4 v = *reinterpret_cast<const float4*>(&A[(size_t)ar * lda + kt + ac * 4]);
            As[ac * 4 + 0][ar] = v.x;
            As[ac * 4 + 1][ar] = v.y;
            As[ac * 4 + 2][ar] = v.z;
            As[ac * 4 + 3][ar] = v.w;
        }
        // Load B tile [BK x BN]
#pragma unroll
        for (int l = 0; l < BK * BN / (THREADS * 4); l++) {
            int idx = tid + l * THREADS;
            int br = idx / (BN / 4);
            int bc = idx % (BN / 4);
            *reinterpret_cast<float4*>(&Bs[br][bc * 4]) =
                *reinterpret_cast<const float4*>(&B[(size_t)(kt + br) * ldb + bc * 4]);
        }
        __syncthreads();
#pragma unroll
        for (int k = 0; k < BK; k++) {
            float af[TM], bf[TN];
#pragma unroll
            for (int i = 0; i < TM; i++) af[i] = As[k][trow * TM + i];
#pragma unroll
            for (int j = 0; j < TN; j++) bf[j] = Bs[k][tcol * TN + j];
#pragma unroll
            for (int i = 0; i < TM; i++)
#pragma unroll
                for (int j = 0; j < TN; j++) acc[i][j] += af[i] * bf[j];
        }
        __syncthreads();
    }

    C += (size_t)row0 * ldc + col0;
#pragma unroll
    for (int i = 0; i < TM; i++) {
        int r = trow * TM + i;
#pragma unroll
        for (int j = 0; j < TN; j++) {
            int c = tcol * TN + j;
            float v = acc[i][j] + bias[col0 + c];
            if (RELU) v = fmaxf(v, 0.f);
            C[(size_t)r * ldc + c] = v;
        }
    }
}

// ---------------------------------------------------------------------------
// Scores: attn_raw[b,h,q,k] = (Q[b,q,h,:] . K[b,k,h,:]) / 8, masked.
// Q/K layout: [B, S, 768] with head h occupying columns h*64..h*64+63.
// ---------------------------------------------------------------------------
template <int BM, int BN, int BK>
__global__ void __launch_bounds__(256)
scores_kernel(const float* __restrict__ Qm, const float* __restrict__ Km,
              const unsigned char* __restrict__ mask, float* __restrict__ attn)
{
    constexpr int TM = 8, TN = 8;
    constexpr int THREADS = (BM / TM) * (BN / TN);
    __shared__ float As[BK][BM];
    __shared__ float Bs[BK][BN];

    const int z = blockIdx.z;
    const int b = z / N_HEADS;
    const int h = z % N_HEADS;
    const int tid  = threadIdx.x;
    const int tcol = tid % (BN / TN);
    const int trow = tid / (BN / TN);

    const float* A  = Qm + (size_t)b * SEQ * D_MODEL + h * D_KH + (size_t)blockIdx.y * BM * D_MODEL;
    const float* Bp = Km + (size_t)b * SEQ * D_MODEL + h * D_KH + (size_t)blockIdx.x * BN * D_MODEL;
    float* C = attn + (size_t)z * SEQ * SEQ + (size_t)blockIdx.y * BM * SEQ + (size_t)blockIdx.x * BN;
    const unsigned char* Mp = mask + (size_t)b * SEQ * SEQ + (size_t)blockIdx.y * BM * SEQ + (size_t)blockIdx.x * BN;

    float acc[TM][TN];
#pragma unroll
    for (int i = 0; i < TM; i++)
#pragma unroll
        for (int j = 0; j < TN; j++) acc[i][j] = 0.f;

    for (int kt = 0; kt < D_KH; kt += BK) {
#pragma unroll
        for (int l = 0; l < BM * BK / (THREADS * 4); l++) {
            int idx = tid + l * THREADS;
            int ar = idx / (BK / 4);
            int ac = idx % (BK / 4);
            float4 v = *reinterpret_cast<const float4*>(&A[(size_t)ar * D_MODEL + kt + ac * 4]);
            As[ac * 4 + 0][ar] = v.x;
            As[ac * 4 + 1][ar] = v.y;
            As[ac * 4 + 2][ar] = v.z;
            As[ac * 4 + 3][ar] = v.w;
        }
#pragma unroll
        for (int l = 0; l < BN * BK / (THREADS * 4); l++) {
            int idx = tid + l * THREADS;
            int bn = idx / (BK / 4);
            int bc = idx % (BK / 4);
            float4 v = *reinterpret_cast<const float4*>(&Bp[(size_t)bn * D_MODEL + kt + bc * 4]);
            Bs[bc * 4 + 0][bn] = v.x;
            Bs[bc * 4 + 1][bn] = v.y;
            Bs[bc * 4 + 2][bn] = v.z;
            Bs[bc * 4 + 3][bn] = v.w;
        }
        __syncthreads();
#pragma unroll
        for (int k = 0; k < BK; k++) {
            float af[TM], bf[TN];
#pragma unroll
            for (int i = 0; i < TM; i++) af[i] = As[k][trow * TM + i];
#pragma unroll
            for (int j = 0; j < TN; j++) bf[j] = Bs[k][tcol * TN + j];
#pragma unroll
            for (int i = 0; i < TM; i++)
#pragma unroll
                for (int j = 0; j < TN; j++) acc[i][j] += af[i] * bf[j];
        }
        __syncthreads();
    }

#pragma unroll
    for (int i = 0; i < TM; i++) {
        int r = trow * TM + i;
#pragma unroll
        for (int j = 0; j < TN; j++) {
            int c = tcol * TN + j;
            float v = acc[i][j] * 0.125f;           // 1/sqrt(64)
            if (Mp[(size_t)r * SEQ + c]) v = -1e9f;
            C[(size_t)r * SEQ + c] = v;
        }
    }
}

// ---------------------------------------------------------------------------
// Row softmax in-place, row length 2048. One block (256 threads) per row.
// ---------------------------------------------------------------------------
__device__ __forceinline__ float warp_max(float v) {
#pragma unroll
    for (int o = 16; o; o >>= 1) v = fmaxf(v, __shfl_xor_sync(0xffffffffu, v, o));
    return v;
}
__device__ __forceinline__ float warp_sum(float v) {
#pragma unroll
    for (int o = 16; o; o >>= 1) v += __shfl_xor_sync(0xffffffffu, v, o);
    return v;
}

__global__ void __launch_bounds__(256)
softmax_kernel(float* __restrict__ attn)
{
    __shared__ float smax[8];
    __shared__ float ssum[8];
    const size_t row = blockIdx.x;
    float* p = attn + row * SEQ;
    const int tid = threadIdx.x;
    const int lane = tid & 31;
    const int wid = tid >> 5;

    float4 v0 = reinterpret_cast<float4*>(p)[tid];
    float4 v1 = reinterpret_cast<float4*>(p)[tid + 256];

    float m = fmaxf(fmaxf(fmaxf(v0.x, v0.y), fmaxf(v0.z, v0.w)),
                    fmaxf(fmaxf(v1.x, v1.y), fmaxf(v1.z, v1.w)));
    m = warp_max(m);
    if (lane == 0) smax[wid] = m;
    __syncthreads();
    float bm = smax[0];
#pragma unroll
    for (int i = 1; i < 8; i++) bm = fmaxf(bm, smax[i]);

    v0.x = expf(v0.x - bm); v0.y = expf(v0.y - bm);
    v0.z = expf(v0.z - bm); v0.w = expf(v0.w - bm);
    v1.x = expf(v1.x - bm); v1.y = expf(v1.y - bm);
    v1.z = expf(v1.z - bm); v1.w = expf(v1.w - bm);

    float s = v0.x + v0.y + v0.z + v0.w + v1.x + v1.y + v1.z + v1.w;
    s = warp_sum(s);
    if (lane == 0) ssum[wid] = s;
    __syncthreads();
    float bs = 0.f;
#pragma unroll
    for (int i = 0; i < 8; i++) bs += ssum[i];
    float inv = 1.0f / bs;

    v0.x *= inv; v0.y *= inv; v0.z *= inv; v0.w *= inv;
    v1.x *= inv; v1.y *= inv; v1.z *= inv; v1.w *= inv;
    reinterpret_cast<float4*>(p)[tid]       = v0;
    reinterpret_cast<float4*>(p)[tid + 256] = v1;
}

// ---------------------------------------------------------------------------
// Context: ctx[b,q,h,:] = sum_k attn[b,h,q,k] * V[b,k,h,:]
// Per (b,h): GEMM M=2048, N=64, K=2048.
// ---------------------------------------------------------------------------
template <int BM, int BN, int BK, int TM, int TN>
__global__ void __launch_bounds__(256)
context_kernel(const float* __restrict__ P, const float* __restrict__ Vm,
               float* __restrict__ C)
{
    constexpr int THREADS = (BM / TM) * (BN / TN);
    __shared__ float As[BK][BM];
    __shared__ float Bs[BK][BN];

    const int z = blockIdx.z;
    const int b = z / N_HEADS;
    const int h = z % N_HEADS;
    const int tid  = threadIdx.x;
    const int tcol = tid % (BN / TN);
    const int trow = tid / (BN / TN);

    const float* A  = P + (size_t)z * SEQ * SEQ + (size_t)blockIdx.y * BM * SEQ;
    const float* Bp = Vm + (size_t)b * SEQ * D_MODEL + h * D_KH;
    float* Cp = C + (size_t)b * SEQ * D_MODEL + h * D_KH + (size_t)blockIdx.y * BM * D_MODEL;

    float acc[TM][TN];
#pragma unroll
    for (int i = 0; i < TM; i++)
#pragma unroll
        for (int j = 0; j < TN; j++) acc[i][j] = 0.f;

    for (int kt = 0; kt < SEQ; kt += BK) {
#pragma unroll
        for (int l = 0; l < BM * BK / (THREADS * 4); l++) {
            int idx = tid + l * THREADS;
            int ar = idx / (BK / 4);
            int ac = idx % (BK / 4);
            float4 v = *reinterpret_cast<const float4*>(&A[(size_t)ar * SEQ + kt + ac * 4]);
            As[ac * 4 + 0][ar] = v.x;
            As[ac * 4 + 1][ar] = v.y;
            As[ac * 4 + 2][ar] = v.z;
            As[ac * 4 + 3][ar] = v.w;
        }
#pragma unroll
        for (int l = 0; l < BK * BN / (THREADS * 4); l++) {
            int idx = tid + l * THREADS;
            int br = idx / (BN / 4);
            int bc = idx % (BN / 4);
            *reinterpret_cast<float4*>(&Bs[br][bc * 4]) =
                *reinterpret_cast<const float4*>(&Bp[(size_t)(kt + br) * D_MODEL + bc * 4]);
        }
        __syncthreads();
#pragma unroll
        for (int k = 0; k < BK; k++) {
            float af[TM], bf[TN];
#pragma unroll
            for (int i = 0; i < TM; i++) af[i] = As[k][trow * TM + i];
#pragma unroll
            for (int j = 0; j < TN; j++) bf[j] = Bs[k][tcol * TN + j];
#pragma unroll
            for (int i = 0; i < TM; i++)
#pragma unroll
                for (int j = 0; j < TN; j++) acc[i][j] += af[i] * bf[j];
        }
        __syncthreads();
    }

#pragma unroll
    for (int i = 0; i < TM; i++) {
        int r = trow * TM + i;
#pragma unroll
        for (int j = 0; j < TN; j++) {
            int c = tcol * TN + j;
            Cp[(size_t)r * D_MODEL + c] = acc[i][j];
        }
    }
}

// ---------------------------------------------------------------------------
// LayerNorm: out[row,:] = LN(x[row,:] + resid[row,:]) * gamma + beta
// One block (256 threads) per row of 768.
// ---------------------------------------------------------------------------
__global__ void __launch_bounds__(256)
ln_kernel(const float* __restrict__ x, const float* __restrict__ resid,
          const float* __restrict__ gamma, const float* __restrict__ beta,
          float* __restrict__ out)
{
    __shared__ float s_s[8];
    __shared__ float s_ss[8];
    const int row = blockIdx.x;
    const int tid = threadIdx.x;
    const int lane = tid & 31;
    const int wid = tid >> 5;
    const float* xr = x + (size_t)row * D_MODEL;
    const float* rr = resid + (size_t)row * D_MODEL;

    float v[3];
    float s = 0.f, ss = 0.f;
#pragma unroll
    for (int i = 0; i < 3; i++) {
        int c = tid + i * 256;
        v[i] = xr[c] + rr[c];
        s  += v[i];
        ss += v[i] * v[i];
    }
    s = warp_sum(s);
    ss = warp_sum(ss);
    if (lane == 0) { s_s[wid] = s; s_ss[wid] = ss; }
    __syncthreads();
    float ts = 0.f, tss = 0.f;
#pragma unroll
    for (int i = 0; i < 8; i++) { ts += s_s[i]; tss += s_ss[i]; }
    const float mean = ts * (1.0f / D_MODEL);
    const float var  = tss * (1.0f / D_MODEL) - mean * mean;
    const float inv  = rsqrtf(var + 1e-5f);

#pragma unroll
    for (int i = 0; i < 3; i++) {
        int c = tid + i * 256;
        out[(size_t)row * D_MODEL + c] = (v[i] - mean) * inv * gamma[c] + beta[c];
    }
}

// ---------------------------------------------------------------------------
// Launch
// ---------------------------------------------------------------------------
extern "C" void kernel_launch(void* const* d_in, const int* in_sizes, int n_in,
                              void* d_out, int out_size)
{
    const float* X              = (const float*)d_in[0];
    const unsigned char* mask   = (const unsigned char*)d_in[1];
    const float* Wq = (const float*)d_in[2];
    const float* bq = (const float*)d_in[3];
    const float* Wk = (const float*)d_in[4];
    const float* bk = (const float*)d_in[5];
    const float* Wv = (const float*)d_in[6];
    const float* bv = (const float*)d_in[7];
    const float* Wo = (const float*)d_in[8];
    const float* bo = (const float*)d_in[9];
    const float* ln1g = (const float*)d_in[10];
    const float* ln1b = (const float*)d_in[11];
    const float* W1 = (const float*)d_in[12];
    const float* b1 = (const float*)d_in[13];
    const float* W2 = (const float*)d_in[14];
    const float* b2 = (const float*)d_in[15];
    const float* ln2g = (const float*)d_in[16];
    const float* ln2b = (const float*)d_in[17];

    float* out  = (float*)d_out;
    float* attn = out + OUT_ELEMS;

    float *q, *k, *v, *ctx, *t1, *ao, *ffn, *t2;
    cudaGetSymbolAddress((void**)&q,   g_q);
    cudaGetSymbolAddress((void**)&k,   g_k);
    cudaGetSymbolAddress((void**)&v,   g_v);
    cudaGetSymbolAddress((void**)&ctx, g_ctx);
    cudaGetSymbolAddress((void**)&t1,  g_t1);
    cudaGetSymbolAddress((void**)&ao,  g_ao);
    cudaGetSymbolAddress((void**)&ffn, g_ffn);
    cudaGetSymbolAddress((void**)&t2,  g_t2);

    // QKV projections: [4096,768] @ [768,768] + bias
    dim3 g768(D_MODEL / 128, ROWS / 128);
    gemm_bias_kernel<128,128,16,8,8,false><<<g768, 256>>>(X, D_MODEL, Wq, D_MODEL, q, D_MODEL, bq, D_MODEL);
    gemm_bias_kernel<128,128,16,8,8,false><<<g768, 256>>>(X, D_MODEL, Wk, D_MODEL, k, D_MODEL, bk, D_MODEL);
    gemm_bias_kernel<128,128,16,8,8,false><<<g768, 256>>>(X, D_MODEL, Wv, D_MODEL, v, D_MODEL, bv, D_MODEL);

    // Attention scores (raw, masked) -> attn region of d_out
    scores_kernel<128,128,16><<<dim3(SEQ / 128, SEQ / 128, BATCH * N_HEADS), 256>>>(q, k, mask, attn);

    // Softmax in-place over last dim
    softmax_kernel<<<BATCH * N_HEADS * SEQ, 256>>>(attn);

    // Context: attn @ V
    context_kernel<128,64,16,8,4><<<dim3(1, SEQ / 128, BATCH * N_HEADS), 256>>>(attn, v, ctx);

    // Output projection + LN1 (residual = enc_inputs)
    gemm_bias_kernel<128,128,16,8,8,false><<<g768, 256>>>(ctx, D_MODEL, Wo, D_MODEL, t1, D_MODEL, bo, D_MODEL);
    ln_kernel<<<ROWS, 256>>>(t1, X, ln1g, ln1b, ao);

    // FFN
    gemm_bias_kernel<128,128,16,8,8,true><<<dim3(D_FF / 128, ROWS / 128), 256>>>(ao, D_MODEL, W1, D_FF, ffn, D_FF, b1, D_MODEL);
    gemm_bias_kernel<128,128,16,8,8,false><<<g768, 256>>>(ffn, D_FF, W2, D_MODEL, t2, D_MODEL, b2, D_FF);

    // LN2 (residual = attn_out) -> out region of d_out
    ln_kernel<<<ROWS, 256>>>(t2, ao, ln2g, ln2b, out);
}

// round 2
// speedup vs baseline: 1.0028x; 1.0028x over previous
#include <cuda_runtime.h>
#include <math.h>

#define D_MODEL 768
#define N_HEADS 12
#define D_FF    3072
#define D_KH    64
#define BATCH   2
#define SEQ     2048
#define ROWS    (BATCH * SEQ)
#define OUT_ELEMS ((size_t)ROWS * D_MODEL)

// Scratch
__device__ float g_q[ROWS * D_MODEL];
__device__ float g_k[ROWS * D_MODEL];
__device__ float g_v[ROWS * D_MODEL];
__device__ float g_ctx[ROWS * D_MODEL];
__device__ float g_t1[ROWS * D_MODEL];
__device__ float g_ao[ROWS * D_MODEL];
__device__ float g_ffn[ROWS * D_FF];
__device__ float g_t2[ROWS * D_MODEL];

// ---------------------------------------------------------------------------
// Packed f32x2 helpers (FFMA2 is only reachable via PTX fma.rn.f32x2)
// ---------------------------------------------------------------------------
typedef unsigned long long u64;

__device__ __forceinline__ u64 dup_f32x2(float a) {
    u64 r;
    asm("mov.b64 %0, {%1, %1};" : "=l"(r) : "r"(__float_as_uint(a)));
    return r;
}
__device__ __forceinline__ void fma_f32x2(u64& d, u64 a, u64 b) {
    asm("fma.rn.f32x2 %0, %1, %2, %0;" : "+l"(d) : "l"(a), "l"(b));
}
__device__ __forceinline__ float2 unpack_f32x2(u64 v) {
    float2 r;
    asm("mov.b64 {%0, %1}, %2;" : "=f"(r.x), "=f"(r.y) : "l"(v));
    return r;
}

__device__ __forceinline__ float warp_sum(float v) {
#pragma unroll
    for (int o = 16; o; o >>= 1) v += __shfl_xor_sync(0xffffffffu, v, o);
    return v;
}

// ---------------------------------------------------------------------------
// Generic NN GEMM with packed f32x2 accumulation:
// C[M,N] = A[M,K] @ B[K,N] + bias, optional ReLU.
// BM=128 BN=128 BK=16, TM=8 TN=8 (4 packed pairs), 256 threads.
// ---------------------------------------------------------------------------
template <int BM, int BN, int BK, int TM, int TN, bool RELU>
__global__ void __launch_bounds__(256)
gemm_bias_kernel(const float* __restrict__ A, int lda,
                 const float* __restrict__ B, int ldb,
                 float* __restrict__ C, int ldc,
                 const float* __restrict__ bias, int K)
{
    constexpr int THREADS = (BM / TM) * (BN / TN);
    static_assert(THREADS == 256, "256 threads required");
    constexpr int NP = TN / 2;
    __shared__ float As[BK][BM];
    __shared__ float Bs[BK][BN];

    const int tid  = threadIdx.x;
    const int tcol = tid % (BN / TN);
    const int trow = tid / (BN / TN);
    const int row0 = blockIdx.y * BM;
    const int col0 = blockIdx.x * BN;

    A += (size_t)row0 * lda;
    B += col0;

    u64 acc[TM][NP];
#pragma unroll
    for (int i = 0; i < TM; i++)
#pragma unroll
        for (int j = 0; j < NP; j++) acc[i][j] = 0ull;

    for (int kt = 0; kt < K; kt += BK) {
#pragma unroll
        for (int l = 0; l < BM * BK / (THREADS * 4); l++) {
            int idx = tid + l * THREADS;
            int ar = idx / (BK / 4);
            int ac = idx % (BK / 4);
            float4 v = *reinterpret_cast<const float4*>(&A[(size_t)ar * lda + kt + ac * 4]);
            As[ac * 4 + 0][ar] = v.x;
            As[ac * 4 + 1][ar] = v.y;
            As[ac * 4 + 2][ar] = v.z;
            As[ac * 4 + 3][ar] = v.w;
        }
#pragma unroll
        for (int l = 0; l < BK * BN / (THREADS * 4); l++) {
            int idx = tid + l * THREADS;
            int br = idx / (BN / 4);
            int bc = idx % (BN / 4);
            *reinterpret_cast<float4*>(&Bs[br][bc * 4]) =
                *reinterpret_cast<const float4*>(&B[(size_t)(kt + br) * ldb + bc * 4]);
        }
        __syncthreads();
#pragma unroll
        for (int k = 0; k < BK; k++) {
            u64 ap[TM], bp[NP];
#pragma unroll
            for (int i = 0; i < TM; i++) ap[i] = dup_f32x2(As[k][trow * TM + i]);
            const u64* b64 = reinterpret_cast<const u64*>(&Bs[k][tcol * TN]);
#pragma unroll
            for (int j = 0; j < NP; j++) bp[j] = b64[j];
#pragma unroll
            for (int i = 0; i < TM; i++)
#pragma unroll
                for (int j = 0; j < NP; j++) fma_f32x2(acc[i][j], ap[i], bp[j]);
        }
        __syncthreads();
    }

    C += (size_t)row0 * ldc + col0;
#pragma unroll
    for (int i = 0; i < TM; i++) {
        int r = trow * TM + i;
#pragma unroll
        for (int j = 0; j < NP; j++) {
            int c = tcol * TN + 2 * j;
            float2 u = unpack_f32x2(acc[i][j]);
            float v0 = u.x + bias[col0 + c];
            float v1 = u.y + bias[col0 + c + 1];
            if (RELU) { v0 = fmaxf(v0, 0.f); v1 = fmaxf(v1, 0.f); }
            C[(size_t)r * ldc + c]     = v0;
            C[(size_t)r * ldc + c + 1] = v1;
        }
    }
}

// ---------------------------------------------------------------------------
// Scores: attn_raw[b,h,q,k] = (Q . K)/8, masked. f32x2 accumulation.
// ---------------------------------------------------------------------------
template <int BM, int BN, int BK>
__global__ void __launch_bounds__(256)
scores_kernel(const float* __restrict__ Qm, const float* __restrict__ Km,
              const unsigned char* __restrict__ mask, float* __restrict__ attn)
{
    constexpr int TM = 8, TN = 8, NP = TN / 2;
    constexpr int THREADS = (BM / TM) * (BN / TN);
    __shared__ float As[BK][BM];
    __shared__ float Bs[BK][BN];

    const int z = blockIdx.z;
    const int b = z / N_HEADS;
    const int h = z % N_HEADS;
    const int tid  = threadIdx.x;
    const int tcol = tid % (BN / TN);
    const int trow = tid / (BN / TN);

    const float* A  = Qm + (size_t)b * SEQ * D_MODEL + h * D_KH + (size_t)blockIdx.y * BM * D_MODEL;
    const float* Bp = Km + (size_t)b * SEQ * D_MODEL + h * D_KH + (size_t)blockIdx.x * BN * D_MODEL;
    float* C = attn + (size_t)z * SEQ * SEQ + (size_t)blockIdx.y * BM * SEQ + (size_t)blockIdx.x * BN;
    const unsigned char* Mp = mask + (size_t)b * SEQ * SEQ + (size_t)blockIdx.y * BM * SEQ + (size_t)blockIdx.x * BN;

    u64 acc[TM][NP];
#pragma unroll
    for (int i = 0; i < TM; i++)
#pragma unroll
        for (int j = 0; j < NP; j++) acc[i][j] = 0ull;

    for (int kt = 0; kt < D_KH; kt += BK) {
#pragma unroll
        for (int l = 0; l < BM * BK / (THREADS * 4); l++) {
            int idx = tid + l * THREADS;
            int ar = idx / (BK / 4);
            int ac = idx % (BK / 4);
            float4 v = *reinterpret_cast<const float4*>(&A[(size_t)ar * D_MODEL + kt + ac * 4]);
            As[ac * 4 + 0][ar] = v.x;
            As[ac * 4 + 1][ar] = v.y;
            As[ac * 4 + 2][ar] = v.z;
            As[ac * 4 + 3][ar] = v.w;
        }
#pragma unroll
        for (int l = 0; l < BN * BK / (THREADS * 4); l++) {
            int idx = tid + l * THREADS;
            int bn = idx / (BK / 4);
            int bc = idx % (BK / 4);
            float4 v = *reinterpret_cast<const float4*>(&Bp[(size_t)bn * D_MODEL + kt + bc * 4]);
            Bs[bc * 4 + 0][bn] = v.x;
            Bs[bc * 4 + 1][bn] = v.y;
            Bs[bc * 4 + 2][bn] = v.z;
            Bs[bc * 4 + 3][bn] = v.w;
        }
        __syncthreads();
#pragma unroll
        for (int k = 0; k < BK; k++) {
            u64 ap[TM], bp[NP];
#pragma unroll
            for (int i = 0; i < TM; i++) ap[i] = dup_f32x2(As[k][trow * TM + i]);
            const u64* b64 = reinterpret_cast<const u64*>(&Bs[k][tcol * TN]);
#pragma unroll
            for (int j = 0; j < NP; j++) bp[j] = b64[j];
#pragma unroll
            for (int i = 0; i < TM; i++)
#pragma unroll
                for (int j = 0; j < NP; j++) fma_f32x2(acc[i][j], ap[i], bp[j]);
        }
        __syncthreads();
    }

#pragma unroll
    for (int i = 0; i < TM; i++) {
        int r = trow * TM + i;
#pragma unroll
        for (int j = 0; j < NP; j++) {
            int c = tcol * TN + 2 * j;
            float2 u = unpack_f32x2(acc[i][j]);
            float v0 = u.x * 0.125f;
            float v1 = u.y * 0.125f;
            if (Mp[(size_t)r * SEQ + c])     v0 = -1e9f;
            if (Mp[(size_t)r * SEQ + c + 1]) v1 = -1e9f;
            C[(size_t)r * SEQ + c]     = v0;
            C[(size_t)r * SEQ + c + 1] = v1;
        }
    }
}

// ---------------------------------------------------------------------------
// Fused softmax + context:
//   pre-pass: inv[r] = 1/sum_k exp(raw[r][k])  (no max-shift; scores are O(1),
//             masked entries are -1e9 -> exp = 0)
//   main GEMM: p = exp(raw)*inv is used as A operand AND written in place over
//              the raw scores (block owns its 128 rows; only already-consumed
//              columns are overwritten).
// ctx[b,q,h,:] = sum_k p[b,h,q,k] * V[b,k,h,:]
// BM=128 BN=64 BK=16, TM=8 TN=4 (2 pairs), 256 threads.
// ---------------------------------------------------------------------------
template <int BM, int BN, int BK, int TM, int TN>
__global__ void __launch_bounds__(256)
softmax_context_kernel(float* __restrict__ attn, const float* __restrict__ Vm,
                       float* __restrict__ C)
{
    constexpr int THREADS = (BM / TM) * (BN / TN);
    static_assert(THREADS == 256, "256 threads required");
    constexpr int NP = TN / 2;
    __shared__ float As[BK][BM];
    __shared__ float Bs[BK][BN];
    __shared__ float sinv[BM];

    const int z = blockIdx.z;
    const int b = z / N_HEADS;
    const int h = z % N_HEADS;
    const int tid  = threadIdx.x;
    const int tcol = tid % (BN / TN);
    const int trow = tid / (BN / TN);

    float* Araw = attn + (size_t)z * SEQ * SEQ + (size_t)blockIdx.y * BM * SEQ;
    const float* Bp = Vm + (size_t)b * SEQ * D_MODEL + h * D_KH;
    float* Cp = C + (size_t)b * SEQ * D_MODEL + h * D_KH + (size_t)blockIdx.y * BM * D_MODEL;

    // Pre-pass: row sums of exp(raw). 8 warps, each handles rows w, w+8, ...
    {
        const int w = tid >> 5, lane = tid & 31;
        for (int r = w; r < BM; r += 8) {
            const float* rp = Araw + (size_t)r * SEQ;
            float s = 0.f;
#pragma unroll
            for (int it = 0; it < SEQ / 128; it++) {
                float4 v = *reinterpret_cast<const float4*>(&rp[it * 128 + lane * 4]);
                s += __expf(v.x) + __expf(v.y) + __expf(v.z) + __expf(v.w);
            }
            s = warp_sum(s);
            if (lane == 0) sinv[r] = 1.0f / s;
        }
    }
    __syncthreads();

    u64 acc[TM][NP];
#pragma unroll
    for (int i = 0; i < TM; i++)
#pragma unroll
        for (int j = 0; j < NP; j++) acc[i][j] = 0ull;

    for (int kt = 0; kt < SEQ; kt += BK) {
        // Load raw scores tile, convert to probs, stage transposed + write back.
#pragma unroll
        for (int l = 0; l < BM * BK / (THREADS * 4); l++) {
            int idx = tid + l * THREADS;
            int ar = idx / (BK / 4);
            int ac = idx % (BK / 4);
            float* gp = &Araw[(size_t)ar * SEQ + kt + ac * 4];
            float4 v = *reinterpret_cast<const float4*>(gp);
            float inv = sinv[ar];
            v.x = __expf(v.x) * inv;
            v.y = __expf(v.y) * inv;
            v.z = __expf(v.z) * inv;
            v.w = __expf(v.w) * inv;
            As[ac * 4 + 0][ar] = v.x;
            As[ac * 4 + 1][ar] = v.y;
            As[ac * 4 + 2][ar] = v.z;
            As[ac * 4 + 3][ar] = v.w;
            *reinterpret_cast<float4*>(gp) = v;   // final attn output
        }
#pragma unroll
        for (int l = 0; l < BK * BN / (THREADS * 4); l++) {
            int idx = tid + l * THREADS;
            int br = idx / (BN / 4);
            int bc = idx % (BN / 4);
            *reinterpret_cast<float4*>(&Bs[br][bc * 4]) =
                *reinterpret_cast<const float4*>(&Bp[(size_t)(kt + br) * D_MODEL + bc * 4]);
        }
        __syncthreads();
#pragma unroll
        for (int k = 0; k < BK; k++) {
            u64 ap[TM], bp[NP];
#pragma unroll
            for (int i = 0; i < TM; i++) ap[i] = dup_f32x2(As[k][trow * TM + i]);
            const u64* b64 = reinterpret_cast<const u64*>(&Bs[k][tcol * TN]);
#pragma unroll
            for (int j = 0; j < NP; j++) bp[j] = b64[j];
#pragma unroll
            for (int i = 0; i < TM; i++)
#pragma unroll
                for (int j = 0; j < NP; j++) fma_f32x2(acc[i][j], ap[i], bp[j]);
        }
        __syncthreads();
    }

#pragma unroll
    for (int i = 0; i < TM; i++) {
        int r = trow * TM + i;
#pragma unroll
        for (int j = 0; j < NP; j++) {
            int c = tcol * TN + 2 * j;
            float2 u = unpack_f32x2(acc[i][j]);
            Cp[(size_t)r * D_MODEL + c]     = u.x;
            Cp[(size_t)r * D_MODEL + c + 1] = u.y;
        }
    }
}

// ---------------------------------------------------------------------------
// LayerNorm: out[row,:] = LN(x[row,:] + resid[row,:]) * gamma + beta
// ---------------------------------------------------------------------------
__global__ void __launch_bounds__(256)
ln_kernel(const float* __restrict__ x, const float* __restrict__ resid,
          const float* __restrict__ gamma, const float* __restrict__ beta,
          float* __restrict__ out)
{
    __shared__ float s_s[8];
    __shared__ float s_ss[8];
    const int row = blockIdx.x;
    const int tid = threadIdx.x;
    const int lane = tid & 31;
    const int wid = tid >> 5;
    const float* xr = x + (size_t)row * D_MODEL;
    const float* rr = resid + (size_t)row * D_MODEL;

    float v[3];
    float s = 0.f, ss = 0.f;
#pragma unroll
    for (int i = 0; i < 3; i++) {
        int c = tid + i * 256;
        v[i] = xr[c] + rr[c];
        s  += v[i];
        ss += v[i] * v[i];
    }
    s = warp_sum(s);
    ss = warp_sum(ss);
    if (lane == 0) { s_s[wid] = s; s_ss[wid] = ss; }
    __syncthreads();
    float ts = 0.f, tss = 0.f;
#pragma unroll
    for (int i = 0; i < 8; i++) { ts += s_s[i]; tss += s_ss[i]; }
    const float mean = ts * (1.0f / D_MODEL);
    const float var  = tss * (1.0f / D_MODEL) - mean * mean;
    const float inv  = rsqrtf(var + 1e-5f);

#pragma unroll
    for (int i = 0; i < 3; i++) {
        int c = tid + i * 256;
        out[(size_t)row * D_MODEL + c] = (v[i] - mean) * inv * gamma[c] + beta[c];
    }
}

// ---------------------------------------------------------------------------
// Launch
// ---------------------------------------------------------------------------
extern "C" void kernel_launch(void* const* d_in, const int* in_sizes, int n_in,
                              void* d_out, int out_size)
{
    const float* X              = (const float*)d_in[0];
    const unsigned char* mask   = (const unsigned char*)d_in[1];
    const float* Wq = (const float*)d_in[2];
    const float* bq = (const float*)d_in[3];
    const float* Wk = (const float*)d_in[4];
    const float* bk = (const float*)d_in[5];
    const float* Wv = (const float*)d_in[6];
    const float* bv = (const float*)d_in[7];
    const float* Wo = (const float*)d_in[8];
    const float* bo = (const float*)d_in[9];
    const float* ln1g = (const float*)d_in[10];
    const float* ln1b = (const float*)d_in[11];
    const float* W1 = (const float*)d_in[12];
    const float* b1 = (const float*)d_in[13];
    const float* W2 = (const float*)d_in[14];
    const float* b2 = (const float*)d_in[15];
    const float* ln2g = (const float*)d_in[16];
    const float* ln2b = (const float*)d_in[17];

    float* out  = (float*)d_out;
    float* attn = out + OUT_ELEMS;

    float *q, *k, *v, *ctx, *t1, *ao, *ffn, *t2;
    cudaGetSymbolAddress((void**)&q,   g_q);
    cudaGetSymbolAddress((void**)&k,   g_k);
    cudaGetSymbolAddress((void**)&v,   g_v);
    cudaGetSymbolAddress((void**)&ctx, g_ctx);
    cudaGetSymbolAddress((void**)&t1,  g_t1);
    cudaGetSymbolAddress((void**)&ao,  g_ao);
    cudaGetSymbolAddress((void**)&ffn, g_ffn);
    cudaGetSymbolAddress((void**)&t2,  g_t2);

    dim3 g768(D_MODEL / 128, ROWS / 128);
    gemm_bias_kernel<128,128,16,8,8,false><<<g768, 256>>>(X, D_MODEL, Wq, D_MODEL, q, D_MODEL, bq, D_MODEL);
    gemm_bias_kernel<128,128,16,8,8,false><<<g768, 256>>>(X, D_MODEL, Wk, D_MODEL, k, D_MODEL, bk, D_MODEL);
    gemm_bias_kernel<128,128,16,8,8,false><<<g768, 256>>>(X, D_MODEL, Wv, D_MODEL, v, D_MODEL, bv, D_MODEL);

    scores_kernel<128,128,16><<<dim3(SEQ / 128, SEQ / 128, BATCH * N_HEADS), 256>>>(q, k, mask, attn);

    // softmax fused into context; writes normalized probs into attn in place
    softmax_context_kernel<128,64,16,8,4><<<dim3(1, SEQ / 128, BATCH * N_HEADS), 256>>>(attn, v, ctx);

    gemm_bias_kernel<128,128,16,8,8,false><<<g768, 256>>>(ctx, D_MODEL, Wo, D_MODEL, t1, D_MODEL, bo, D_MODEL);
    ln_kernel<<<ROWS, 256>>>(t1, X, ln1g, ln1b, ao);

    gemm_bias_kernel<128,128,16,8,8,true><<<dim3(D_FF / 128, ROWS / 128), 256>>>(ao, D_MODEL, W1, D_FF, ffn, D_FF, b1, D_MODEL);
    gemm_bias_kernel<128,128,16,8,8,false><<<g768, 256>>>(ffn, D_FF, W2, D_MODEL, t2, D_MODEL, b2, D_FF);

    ln_kernel<<<ROWS, 256>>>(t2, ao, ln2g, ln2b, out);
}

// round 3
// speedup vs baseline: 2.4363x; 2.4294x over previous
#include <cuda_runtime.h>
#include <math.h>
#include <stdint.h>

#define D_MODEL 768
#define N_HEADS 12
#define D_FF    3072
#define D_KH    64
#define BATCH   2
#define SEQ     2048
#define ROWS    (BATCH * SEQ)
#define OUT_ELEMS ((size_t)ROWS * D_MODEL)

// Scratch
__device__ float g_q[ROWS * D_MODEL];
__device__ float g_k[ROWS * D_MODEL];
__device__ float g_v[ROWS * D_MODEL];
__device__ float g_ctx[ROWS * D_MODEL];
__device__ float g_t1[ROWS * D_MODEL];
__device__ float g_ao[ROWS * D_MODEL];
__device__ float g_ffn[ROWS * D_FF];
__device__ float g_t2[ROWS * D_MODEL];

// ---------------------------------------------------------------------------
// TF32 helpers
// ---------------------------------------------------------------------------
__device__ __forceinline__ uint32_t f2tf32(float f) {
    uint32_t r;
    asm("cvt.rna.tf32.f32 %0, %1;" : "=r"(r) : "f"(f));
    return r;
}

__device__ __forceinline__ void mma_tf32(float* c,
                                         uint32_t a0, uint32_t a1, uint32_t a2, uint32_t a3,
                                         uint32_t b0, uint32_t b1) {
    asm("mma.sync.aligned.m16n8k8.row.col.f32.tf32.tf32.f32 "
        "{%0,%1,%2,%3}, {%4,%5,%6,%7}, {%8,%9}, {%0,%1,%2,%3};"
        : "+f"(c[0]), "+f"(c[1]), "+f"(c[2]), "+f"(c[3])
        : "r"(a0), "r"(a1), "r"(a2), "r"(a3), "r"(b0), "r"(b1));
}

__device__ __forceinline__ float warp_sum(float v) {
#pragma unroll
    for (int o = 16; o; o >>= 1) v += __shfl_xor_sync(0xffffffffu, v, o);
    return v;
}

// ---------------------------------------------------------------------------
// Generic NN GEMM body (tf32 tensor cores):
// C[*, col0:col0+BN] tile at row0 = A[M,K](row-major) @ B[K,N](row-major) + bias
// 256 threads, warps 2(M) x 4(N). BM=128 -> warp M tile 64 (MT=4 m16 tiles),
// warp N tile BN/4 (NT = BN/32 n8 tiles).
// ---------------------------------------------------------------------------
template <int BM, int BN, int BK, bool RELU>
__device__ __forceinline__ void gemm_body(const float* __restrict__ A, int lda,
                                          const float* __restrict__ B, int ldb,
                                          float* __restrict__ C, int ldc,
                                          const float* __restrict__ bias, int K,
                                          int row0, int col0)
{
    constexpr int WTM = BM / 2, WTN = BN / 4;
    constexpr int MT = WTM / 16, NT = WTN / 8;
    __shared__ uint32_t As[BM][BK + 4];
    __shared__ uint32_t Bs[BK][BN + 8];

    const int tid = threadIdx.x, lane = tid & 31, wid = tid >> 5;
    const int wm = wid & 1, wn = wid >> 1;
    const int g = lane >> 2, t = lane & 3;

    A += (size_t)row0 * lda;
    B += col0;

    float c[MT][NT][4] = {};

    for (int kt = 0; kt < K; kt += BK) {
#pragma unroll
        for (int l = 0; l < BM * BK / (256 * 4); l++) {
            int idx = tid + l * 256;
            int ar = idx / (BK / 4), ac = idx % (BK / 4);
            float4 v = *reinterpret_cast<const float4*>(&A[(size_t)ar * lda + kt + ac * 4]);
            As[ar][ac * 4 + 0] = f2tf32(v.x);
            As[ar][ac * 4 + 1] = f2tf32(v.y);
            As[ar][ac * 4 + 2] = f2tf32(v.z);
            As[ar][ac * 4 + 3] = f2tf32(v.w);
        }
#pragma unroll
        for (int l = 0; l < BK * BN / (256 * 4); l++) {
            int idx = tid + l * 256;
            int br = idx / (BN / 4), bc = idx % (BN / 4);
            float4 v = *reinterpret_cast<const float4*>(&B[(size_t)(kt + br) * ldb + bc * 4]);
            Bs[br][bc * 4 + 0] = f2tf32(v.x);
            Bs[br][bc * 4 + 1] = f2tf32(v.y);
            Bs[br][bc * 4 + 2] = f2tf32(v.z);
            Bs[br][bc * 4 + 3] = f2tf32(v.w);
        }
        __syncthreads();
#pragma unroll
        for (int kk = 0; kk < BK / 8; kk++) {
            uint32_t a[MT][4], b[NT][2];
#pragma unroll
            for (int mt = 0; mt < MT; mt++) {
                int r = wm * WTM + mt * 16 + g;
                a[mt][0] = As[r][kk * 8 + t];
                a[mt][1] = As[r + 8][kk * 8 + t];
                a[mt][2] = As[r][kk * 8 + t + 4];
                a[mt][3] = As[r + 8][kk * 8 + t + 4];
            }
#pragma unroll
            for (int nt = 0; nt < NT; nt++) {
                int cc = wn * WTN + nt * 8 + g;
                b[nt][0] = Bs[kk * 8 + t][cc];
                b[nt][1] = Bs[kk * 8 + t + 4][cc];
            }
#pragma unroll
            for (int mt = 0; mt < MT; mt++)
#pragma unroll
                for (int nt = 0; nt < NT; nt++)
                    mma_tf32(c[mt][nt], a[mt][0], a[mt][1], a[mt][2], a[mt][3],
                             b[nt][0], b[nt][1]);
        }
        __syncthreads();
    }

    C += (size_t)row0 * ldc + col0;
#pragma unroll
    for (int mt = 0; mt < MT; mt++) {
        int r = wm * WTM + mt * 16 + g;
#pragma unroll
        for (int nt = 0; nt < NT; nt++) {
            int cc = wn * WTN + nt * 8 + 2 * t;
            float b0 = bias[col0 + cc], b1 = bias[col0 + cc + 1];
            float v00 = c[mt][nt][0] + b0, v01 = c[mt][nt][1] + b1;
            float v10 = c[mt][nt][2] + b0, v11 = c[mt][nt][3] + b1;
            if (RELU) {
                v00 = fmaxf(v00, 0.f); v01 = fmaxf(v01, 0.f);
                v10 = fmaxf(v10, 0.f); v11 = fmaxf(v11, 0.f);
            }
            C[(size_t)r * ldc + cc]           = v00;
            C[(size_t)r * ldc + cc + 1]       = v01;
            C[(size_t)(r + 8) * ldc + cc]     = v10;
            C[(size_t)(r + 8) * ldc + cc + 1] = v11;
        }
    }
}

template <int BM, int BN, int BK, bool RELU>
__global__ void __launch_bounds__(256)
gemm_tf32_kernel(const float* __restrict__ A, int lda,
                 const float* __restrict__ B, int ldb,
                 float* __restrict__ C, int ldc,
                 const float* __restrict__ bias, int K)
{
    gemm_body<BM, BN, BK, RELU>(A, lda, B, ldb, C, ldc, bias, K,
                                blockIdx.y * BM, blockIdx.x * BN);
}

// Fused QKV: blockIdx.z selects which projection.
__global__ void __launch_bounds__(256)
qkv_tf32_kernel(const float* __restrict__ X,
                const float* __restrict__ Wq, const float* __restrict__ bq,
                const float* __restrict__ Wk, const float* __restrict__ bk,
                const float* __restrict__ Wv, const float* __restrict__ bv,
                float* __restrict__ q, float* __restrict__ k, float* __restrict__ v)
{
    const float* W; const float* bias; float* C;
    if (blockIdx.z == 0)      { W = Wq; bias = bq; C = q; }
    else if (blockIdx.z == 1) { W = Wk; bias = bk; C = k; }
    else                      { W = Wv; bias = bv; C = v; }
    gemm_body<128, 128, 32, false>(X, D_MODEL, W, D_MODEL, C, D_MODEL, bias, D_MODEL,
                                   blockIdx.y * 128, blockIdx.x * 128);
}

// ---------------------------------------------------------------------------
// Scores: attn_raw[b,h,q,k] = (Q . K)/8, masked. TF32 mma.
// K-tile staged row-major [n][d] (coalesced load), read transposed for B frags.
// ---------------------------------------------------------------------------
template <int BM, int BN, int BK>
__global__ void __launch_bounds__(256)
scores_tf32_kernel(const float* __restrict__ Qm, const float* __restrict__ Km,
                   const unsigned char* __restrict__ mask, float* __restrict__ attn)
{
    constexpr int WTM = BM / 2, WTN = BN / 4;
    constexpr int MT = WTM / 16, NT = WTN / 8;
    __shared__ uint32_t As[BM][BK + 4];
    __shared__ uint32_t Bs[BN][BK + 4];   // [k_seq][d]

    const int z = blockIdx.z;
    const int b = z / N_HEADS;
    const int h = z % N_HEADS;
    const int tid = threadIdx.x, lane = tid & 31, wid = tid >> 5;
    const int wm = wid & 1, wn = wid >> 1;
    const int g = lane >> 2, t = lane & 3;

    const float* A  = Qm + (size_t)b * SEQ * D_MODEL + h * D_KH + (size_t)blockIdx.y * BM * D_MODEL;
    const float* Bp = Km + (size_t)b * SEQ * D_MODEL + h * D_KH + (size_t)blockIdx.x * BN * D_MODEL;
    float* C = attn + (size_t)z * SEQ * SEQ + (size_t)blockIdx.y * BM * SEQ + (size_t)blockIdx.x * BN;
    const unsigned char* Mp = mask + (size_t)b * SEQ * SEQ + (size_t)blockIdx.y * BM * SEQ + (size_t)blockIdx.x * BN;

    float c[MT][NT][4] = {};

    for (int kt = 0; kt < D_KH; kt += BK) {
#pragma unroll
        for (int l = 0; l < BM * BK / (256 * 4); l++) {
            int idx = tid + l * 256;
            int ar = idx / (BK / 4), ac = idx % (BK / 4);
            float4 v = *reinterpret_cast<const float4*>(&A[(size_t)ar * D_MODEL + kt + ac * 4]);
            As[ar][ac * 4 + 0] = f2tf32(v.x);
            As[ar][ac * 4 + 1] = f2tf32(v.y);
            As[ar][ac * 4 + 2] = f2tf32(v.z);
            As[ar][ac * 4 + 3] = f2tf32(v.w);
        }
#pragma unroll
        for (int l = 0; l < BN * BK / (256 * 4); l++) {
            int idx = tid + l * 256;
            int br = idx / (BK / 4), bc = idx % (BK / 4);
            float4 v = *reinterpret_cast<const float4*>(&Bp[(size_t)br * D_MODEL + kt + bc * 4]);
            Bs[br][bc * 4 + 0] = f2tf32(v.x);
            Bs[br][bc * 4 + 1] = f2tf32(v.y);
            Bs[br][bc * 4 + 2] = f2tf32(v.z);
            Bs[br][bc * 4 + 3] = f2tf32(v.w);
        }
        __syncthreads();
#pragma unroll
        for (int kk = 0; kk < BK / 8; kk++) {
            uint32_t a[MT][4], bfr[NT][2];
#pragma unroll
            for (int mt = 0; mt < MT; mt++) {
                int r = wm * WTM + mt * 16 + g;
                a[mt][0] = As[r][kk * 8 + t];
                a[mt][1] = As[r + 8][kk * 8 + t];
                a[mt][2] = As[r][kk * 8 + t + 4];
                a[mt][3] = As[r + 8][kk * 8 + t + 4];
            }
#pragma unroll
            for (int nt = 0; nt < NT; nt++) {
                int cc = wn * WTN + nt * 8 + g;
                bfr[nt][0] = Bs[cc][kk * 8 + t];
                bfr[nt][1] = Bs[cc][kk * 8 + t + 4];
            }
#pragma unroll
            for (int mt = 0; mt < MT; mt++)
#pragma unroll
                for (int nt = 0; nt < NT; nt++)
                    mma_tf32(c[mt][nt], a[mt][0], a[mt][1], a[mt][2], a[mt][3],
                             bfr[nt][0], bfr[nt][1]);
        }
        __syncthreads();
    }

#pragma unroll
    for (int mt = 0; mt < MT; mt++) {
        int r = wm * WTM + mt * 16 + g;
#pragma unroll
        for (int nt = 0; nt < NT; nt++) {
            int cc = wn * WTN + nt * 8 + 2 * t;
            float v00 = c[mt][nt][0] * 0.125f;
            float v01 = c[mt][nt][1] * 0.125f;
            float v10 = c[mt][nt][2] * 0.125f;
            float v11 = c[mt][nt][3] * 0.125f;
            if (Mp[(size_t)r * SEQ + cc])           v00 = -1e9f;
            if (Mp[(size_t)r * SEQ + cc + 1])       v01 = -1e9f;
            if (Mp[(size_t)(r + 8) * SEQ + cc])     v10 = -1e9f;
            if (Mp[(size_t)(r + 8) * SEQ + cc + 1]) v11 = -1e9f;
            C[(size_t)r * SEQ + cc]           = v00;
            C[(size_t)r * SEQ + cc + 1]       = v01;
            C[(size_t)(r + 8) * SEQ + cc]     = v10;
            C[(size_t)(r + 8) * SEQ + cc + 1] = v11;
        }
    }
}

// ---------------------------------------------------------------------------
// Fused softmax + context (TF32 mma for P@V):
//   pre-pass: inv[r] = 1/sum_k exp(raw[r][k]); main loop: p = exp(raw)*inv
//   used as A operand AND written in-place as the final attn output.
// BM=128, BN=64, BK=32. Warps 2x4; warp tile 64 x 16 (NT=2).
// ---------------------------------------------------------------------------
template <int BM, int BN, int BK>
__global__ void __launch_bounds__(256)
smctx_tf32_kernel(float* __restrict__ attn, const float* __restrict__ Vm,
                  float* __restrict__ C)
{
    constexpr int WTM = BM / 2, WTN = BN / 4;
    constexpr int MT = WTM / 16, NT = WTN / 8;
    __shared__ uint32_t As[BM][BK + 4];
    __shared__ uint32_t Bs[BK][BN + 8];
    __shared__ float sinv[BM];

    const int z = blockIdx.z;
    const int b = z / N_HEADS;
    const int h = z % N_HEADS;
    const int tid = threadIdx.x, lane = tid & 31, wid = tid >> 5;
    const int wm = wid & 1, wn = wid >> 1;
    const int g = lane >> 2, t = lane & 3;

    float* Araw = attn + (size_t)z * SEQ * SEQ + (size_t)blockIdx.y * BM * SEQ;
    const float* Bp = Vm + (size_t)b * SEQ * D_MODEL + h * D_KH;
    float* Cp = C + (size_t)b * SEQ * D_MODEL + h * D_KH + (size_t)blockIdx.y * BM * D_MODEL;

    // Pre-pass: row sums of exp(raw).
    {
        for (int r = wid; r < BM; r += 8) {
            const float* rp = Araw + (size_t)r * SEQ;
            float s = 0.f;
#pragma unroll
            for (int it = 0; it < SEQ / 128; it++) {
                float4 v = *reinterpret_cast<const float4*>(&rp[it * 128 + lane * 4]);
                s += __expf(v.x) + __expf(v.y) + __expf(v.z) + __expf(v.w);
            }
            s = warp_sum(s);
            if (lane == 0) sinv[r] = 1.0f / s;
        }
    }
    __syncthreads();

    float c[MT][NT][4] = {};

    for (int kt = 0; kt < SEQ; kt += BK) {
#pragma unroll
        for (int l = 0; l < BM * BK / (256 * 4); l++) {
            int idx = tid + l * 256;
            int ar = idx / (BK / 4), ac = idx % (BK / 4);
            float* gp = &Araw[(size_t)ar * SEQ + kt + ac * 4];
            float4 v = *reinterpret_cast<const float4*>(gp);
            float inv = sinv[ar];
            v.x = __expf(v.x) * inv;
            v.y = __expf(v.y) * inv;
            v.z = __expf(v.z) * inv;
            v.w = __expf(v.w) * inv;
            As[ar][ac * 4 + 0] = f2tf32(v.x);
            As[ar][ac * 4 + 1] = f2tf32(v.y);
            As[ar][ac * 4 + 2] = f2tf32(v.z);
            As[ar][ac * 4 + 3] = f2tf32(v.w);
            *reinterpret_cast<float4*>(gp) = v;   // final attn output
        }
#pragma unroll
        for (int l = 0; l < BK * BN / (256 * 4); l++) {
            int idx = tid + l * 256;
            int br = idx / (BN / 4), bc = idx % (BN / 4);
            float4 v = *reinterpret_cast<const float4*>(&Bp[(size_t)(kt + br) * D_MODEL + bc * 4]);
            Bs[br][bc * 4 + 0] = f2tf32(v.x);
            Bs[br][bc * 4 + 1] = f2tf32(v.y);
            Bs[br][bc * 4 + 2] = f2tf32(v.z);
            Bs[br][bc * 4 + 3] = f2tf32(v.w);
        }
        __syncthreads();
#pragma unroll
        for (int kk = 0; kk < BK / 8; kk++) {
            uint32_t a[MT][4], bfr[NT][2];
#pragma unroll
            for (int mt = 0; mt < MT; mt++) {
                int r = wm * WTM + mt * 16 + g;
                a[mt][0] = As[r][kk * 8 + t];
                a[mt][1] = As[r + 8][kk * 8 + t];
                a[mt][2] = As[r][kk * 8 + t + 4];
                a[mt][3] = As[r + 8][kk * 8 + t + 4];
            }
#pragma unroll
            for (int nt = 0; nt < NT; nt++) {
                int cc = wn * WTN + nt * 8 + g;
                bfr[nt][0] = Bs[kk * 8 + t][cc];
                bfr[nt][1] = Bs[kk * 8 + t + 4][cc];
            }
#pragma unroll
            for (int mt = 0; mt < MT; mt++)
#pragma unroll
                for (int nt = 0; nt < NT; nt++)
                    mma_tf32(c[mt][nt], a[mt][0], a[mt][1], a[mt][2], a[mt][3],
                             bfr[nt][0], bfr[nt][1]);
        }
        __syncthreads();
    }

#pragma unroll
    for (int mt = 0; mt < MT; mt++) {
        int r = wm * WTM + mt * 16 + g;
#pragma unroll
        for (int nt = 0; nt < NT; nt++) {
            int cc = wn * WTN + nt * 8 + 2 * t;
            Cp[(size_t)r * D_MODEL + cc]           = c[mt][nt][0];
            Cp[(size_t)r * D_MODEL + cc + 1]       = c[mt][nt][1];
            Cp[(size_t)(r + 8) * D_MODEL + cc]     = c[mt][nt][2];
            Cp[(size_t)(r + 8) * D_MODEL + cc + 1] = c[mt][nt][3];
        }
    }
}

// ---------------------------------------------------------------------------
// LayerNorm: out[row,:] = LN(x[row,:] + resid[row,:]) * gamma + beta
// ---------------------------------------------------------------------------
__global__ void __launch_bounds__(256)
ln_kernel(const float* __restrict__ x, const float* __restrict__ resid,
          const float* __restrict__ gamma, const float* __restrict__ beta,
          float* __restrict__ out)
{
    __shared__ float s_s[8];
    __shared__ float s_ss[8];
    const int row = blockIdx.x;
    const int tid = threadIdx.x;
    const int lane = tid & 31;
    const int wid = tid >> 5;
    const float* xr = x + (size_t)row * D_MODEL;
    const float* rr = resid + (size_t)row * D_MODEL;

    float v[3];
    float s = 0.f, ss = 0.f;
#pragma unroll
    for (int i = 0; i < 3; i++) {
        int c = tid + i * 256;
        v[i] = xr[c] + rr[c];
        s  += v[i];
        ss += v[i] * v[i];
    }
    s = warp_sum(s);
    ss = warp_sum(ss);
    if (lane == 0) { s_s[wid] = s; s_ss[wid] = ss; }
    __syncthreads();
    float ts = 0.f, tss = 0.f;
#pragma unroll
    for (int i = 0; i < 8; i++) { ts += s_s[i]; tss += s_ss[i]; }
    const float mean = ts * (1.0f / D_MODEL);
    const float var  = tss * (1.0f / D_MODEL) - mean * mean;
    const float inv  = rsqrtf(var + 1e-5f);

#pragma unroll
    for (int i = 0; i < 3; i++) {
        int c = tid + i * 256;
        out[(size_t)row * D_MODEL + c] = (v[i] - mean) * inv * gamma[c] + beta[c];
    }
}

// ---------------------------------------------------------------------------
// Launch
// ---------------------------------------------------------------------------
extern "C" void kernel_launch(void* const* d_in, const int* in_sizes, int n_in,
                              void* d_out, int out_size)
{
    const float* X              = (const float*)d_in[0];
    const unsigned char* mask   = (const unsigned char*)d_in[1];
    const float* Wq = (const float*)d_in[2];
    const float* bq = (const float*)d_in[3];
    const float* Wk = (const float*)d_in[4];
    const float* bk = (const float*)d_in[5];
    const float* Wv = (const float*)d_in[6];
    const float* bv = (const float*)d_in[7];
    const float* Wo = (const float*)d_in[8];
    const float* bo = (const float*)d_in[9];
    const float* ln1g = (const float*)d_in[10];
    const float* ln1b = (const float*)d_in[11];
    const float* W1 = (const float*)d_in[12];
    const float* b1 = (const float*)d_in[13];
    const float* W2 = (const float*)d_in[14];
    const float* b2 = (const float*)d_in[15];
    const float* ln2g = (const float*)d_in[16];
    const float* ln2b = (const float*)d_in[17];

    float* out  = (float*)d_out;
    float* attn = out + OUT_ELEMS;

    float *q, *k, *v, *ctx, *t1, *ao, *ffn, *t2;
    cudaGetSymbolAddress((void**)&q,   g_q);
    cudaGetSymbolAddress((void**)&k,   g_k);
    cudaGetSymbolAddress((void**)&v,   g_v);
    cudaGetSymbolAddress((void**)&ctx, g_ctx);
    cudaGetSymbolAddress((void**)&t1,  g_t1);
    cudaGetSymbolAddress((void**)&ao,  g_ao);
    cudaGetSymbolAddress((void**)&ffn, g_ffn);
    cudaGetSymbolAddress((void**)&t2,  g_t2);

    // Fused QKV projections
    qkv_tf32_kernel<<<dim3(D_MODEL / 128, ROWS / 128, 3), 256>>>(
        X, Wq, bq, Wk, bk, Wv, bv, q, k, v);

    // Attention scores (raw, masked) -> attn region of d_out
    scores_tf32_kernel<128, 128, 32><<<dim3(SEQ / 128, SEQ / 128, BATCH * N_HEADS), 256>>>(
        q, k, mask, attn);

    // Fused softmax + context (writes normalized probs in place)
    smctx_tf32_kernel<128, 64, 32><<<dim3(1, SEQ / 128, BATCH * N_HEADS), 256>>>(
        attn, v, ctx);

    // Output projection + LN1
    dim3 g768(D_MODEL / 128, ROWS / 128);
    gemm_tf32_kernel<128, 128, 32, false><<<g768, 256>>>(ctx, D_MODEL, Wo, D_MODEL, t1, D_MODEL, bo, D_MODEL);
    ln_kernel<<<ROWS, 256>>>(t1, X, ln1g, ln1b, ao);

    // FFN
    gemm_tf32_kernel<128, 128, 32, true ><<<dim3(D_FF / 128, ROWS / 128), 256>>>(ao, D_MODEL, W1, D_FF, ffn, D_FF, b1, D_MODEL);
    gemm_tf32_kernel<128, 128, 32, false><<<g768, 256>>>(ffn, D_FF, W2, D_MODEL, t2, D_MODEL, b2, D_FF);

    ln_kernel<<<ROWS, 256>>>(t2, ao, ln2g, ln2b, out);
}

// round 5
// speedup vs baseline: 2.5767x; 1.0577x over previous
#include <cuda_runtime.h>
#include <math.h>
#include <stdint.h>

#define D_MODEL 768
#define N_HEADS 12
#define D_FF    3072
#define D_KH    64
#define BATCH   2
#define SEQ     2048
#define ROWS    (BATCH * SEQ)
#define OUT_ELEMS ((size_t)ROWS * D_MODEL)
#define NZ (BATCH * N_HEADS)          // 24
#define NBX (SEQ / 128)               // 16 score blocks per row strip

// Scratch
__device__ float g_q[ROWS * D_MODEL];
__device__ float g_k[ROWS * D_MODEL];
__device__ float g_v[ROWS * D_MODEL];
__device__ float g_ctx[ROWS * D_MODEL];
__device__ float g_t1[ROWS * D_MODEL];
__device__ float g_ao[ROWS * D_MODEL];
__device__ float g_ffn[ROWS * D_FF];
__device__ float g_t2[ROWS * D_MODEL];
__device__ float g_part[(size_t)NZ * SEQ * NBX];   // per-block partial row sums of exp

// ---------------------------------------------------------------------------
// TF32 helpers
// ---------------------------------------------------------------------------
__device__ __forceinline__ uint32_t f2tf32(float f) {
    uint32_t r;
    asm("cvt.rna.tf32.f32 %0, %1;" : "=r"(r) : "f"(f));
    return r;
}

__device__ __forceinline__ void mma_tf32(float* c,
                                         uint32_t a0, uint32_t a1, uint32_t a2, uint32_t a3,
                                         uint32_t b0, uint32_t b1) {
    asm("mma.sync.aligned.m16n8k8.row.col.f32.tf32.tf32.f32 "
        "{%0,%1,%2,%3}, {%4,%5,%6,%7}, {%8,%9}, {%0,%1,%2,%3};"
        : "+f"(c[0]), "+f"(c[1]), "+f"(c[2]), "+f"(c[3])
        : "r"(a0), "r"(a1), "r"(a2), "r"(a3), "r"(b0), "r"(b1));
}

// ---------------------------------------------------------------------------
// Pipelined TF32 GEMM body: 2-stage smem double buffer, 1 barrier / k-tile.
// C tile = A[M,K](rm) @ B[K,N](rm) + bias. 256 thr, warps 2(M) x 4(N).
// ---------------------------------------------------------------------------
template <int BM, int BN, int BK, bool RELU>
__device__ __forceinline__ void gemm_body(const float* __restrict__ A, int lda,
                                          const float* __restrict__ B, int ldb,
                                          float* __restrict__ C, int ldc,
                                          const float* __restrict__ bias, int K,
                                          int row0, int col0)
{
    extern __shared__ uint32_t smem[];
    constexpr int A_ST = BK + 4, B_ST = BN + 8;
    constexpr int WTM = BM / 2, WTN = BN / 4;
    constexpr int MT = WTM / 16, NT = WTN / 8;
    constexpr int LA = BM * BK / (256 * 4);
    constexpr int LB = BK * BN / (256 * 4);
    uint32_t* sA = smem;                      // [2][BM][A_ST]
    uint32_t* sB = smem + 2 * BM * A_ST;      // [2][BK][B_ST]

    const int tid = threadIdx.x, lane = tid & 31, wid = tid >> 5;
    const int wm = wid & 1, wn = wid >> 1;
    const int g = lane >> 2, t = lane & 3;

    A += (size_t)row0 * lda;
    B += col0;

    float4 ra[LA], rb[LB];

#define LOADG(kt)                                                              \
    {                                                                          \
        _Pragma("unroll")                                                      \
        for (int l = 0; l < LA; l++) {                                         \
            int idx = tid + l * 256;                                           \
            int ar = idx / (BK / 4), ac = idx % (BK / 4);                      \
            ra[l] = *reinterpret_cast<const float4*>(                          \
                &A[(size_t)ar * lda + (kt) * BK + ac * 4]);                    \
        }                                                                      \
        _Pragma("unroll")                                                      \
        for (int l = 0; l < LB; l++) {                                         \
            int idx = tid + l * 256;                                           \
            int br = idx / (BN / 4), bc = idx % (BN / 4);                      \
            rb[l] = *reinterpret_cast<const float4*>(                          \
                &B[(size_t)((kt) * BK + br) * ldb + bc * 4]);                  \
        }                                                                      \
    }

#define STORES(st)                                                             \
    {                                                                          \
        uint32_t* pA = sA + (st) * BM * A_ST;                                  \
        uint32_t* pB = sB + (st) * BK * B_ST;                                  \
        _Pragma("unroll")                                                      \
        for (int l = 0; l < LA; l++) {                                         \
            int idx = tid + l * 256;                                           \
            int ar = idx / (BK / 4), ac = idx % (BK / 4);                      \
            pA[ar * A_ST + ac * 4 + 0] = f2tf32(ra[l].x);                      \
            pA[ar * A_ST + ac * 4 + 1] = f2tf32(ra[l].y);                      \
            pA[ar * A_ST + ac * 4 + 2] = f2tf32(ra[l].z);                      \
            pA[ar * A_ST + ac * 4 + 3] = f2tf32(ra[l].w);                      \
        }                                                                      \
        _Pragma("unroll")                                                      \
        for (int l = 0; l < LB; l++) {                                         \
            int idx = tid + l * 256;                                           \
            int br = idx / (BN / 4), bc = idx % (BN / 4);                      \
            pB[br * B_ST + bc * 4 + 0] = f2tf32(rb[l].x);                      \
            pB[br * B_ST + bc * 4 + 1] = f2tf32(rb[l].y);                      \
            pB[br * B_ST + bc * 4 + 2] = f2tf32(rb[l].z);                      \
            pB[br * B_ST + bc * 4 + 3] = f2tf32(rb[l].w);                      \
        }                                                                      \
    }

    float c[MT][NT][4] = {};
    const int nk = K / BK;

    LOADG(0);
    STORES(0);

    for (int kt = 1; kt <= nk; kt++) {
        __syncthreads();
        if (kt < nk) LOADG(kt);
        const uint32_t* pA = sA + ((kt - 1) & 1) * BM * A_ST;
        const uint32_t* pB = sB + ((kt - 1) & 1) * BK * B_ST;
#pragma unroll
        for (int kk = 0; kk < BK / 8; kk++) {
            uint32_t a[MT][4], b[NT][2];
#pragma unroll
            for (int mt = 0; mt < MT; mt++) {
                int r = wm * WTM + mt * 16 + g;
                a[mt][0] = pA[r * A_ST + kk * 8 + t];
                a[mt][1] = pA[(r + 8) * A_ST + kk * 8 + t];
                a[mt][2] = pA[r * A_ST + kk * 8 + t + 4];
                a[mt][3] = pA[(r + 8) * A_ST + kk * 8 + t + 4];
            }
#pragma unroll
            for (int nt = 0; nt < NT; nt++) {
                int cc = wn * WTN + nt * 8 + g;
                b[nt][0] = pB[(kk * 8 + t) * B_ST + cc];
                b[nt][1] = pB[(kk * 8 + t + 4) * B_ST + cc];
            }
#pragma unroll
            for (int mt = 0; mt < MT; mt++)
#pragma unroll
                for (int nt = 0; nt < NT; nt++)
                    mma_tf32(c[mt][nt], a[mt][0], a[mt][1], a[mt][2], a[mt][3],
                             b[nt][0], b[nt][1]);
        }
        if (kt < nk) STORES(kt & 1);
    }
#undef LOADG
#undef STORES

    C += (size_t)row0 * ldc + col0;
#pragma unroll
    for (int mt = 0; mt < MT; mt++) {
        int r = wm * WTM + mt * 16 + g;
#pragma unroll
        for (int nt = 0; nt < NT; nt++) {
            int cc = wn * WTN + nt * 8 + 2 * t;
            float b0 = bias[col0 + cc], b1 = bias[col0 + cc + 1];
            float v00 = c[mt][nt][0] + b0, v01 = c[mt][nt][1] + b1;
            float v10 = c[mt][nt][2] + b0, v11 = c[mt][nt][3] + b1;
            if (RELU) {
                v00 = fmaxf(v00, 0.f); v01 = fmaxf(v01, 0.f);
                v10 = fmaxf(v10, 0.f); v11 = fmaxf(v11, 0.f);
            }
            C[(size_t)r * ldc + cc]           = v00;
            C[(size_t)r * ldc + cc + 1]       = v01;
            C[(size_t)(r + 8) * ldc + cc]     = v10;
            C[(size_t)(r + 8) * ldc + cc + 1] = v11;
        }
    }
}

template <int BM, int BN, int BK, bool RELU>
__global__ void __launch_bounds__(256)
gemm_tf32_kernel(const float* __restrict__ A, int lda,
                 const float* __restrict__ B, int ldb,
                 float* __restrict__ C, int ldc,
                 const float* __restrict__ bias, int K)
{
    gemm_body<BM, BN, BK, RELU>(A, lda, B, ldb, C, ldc, bias, K,
                                blockIdx.y * BM, blockIdx.x * BN);
}

__global__ void __launch_bounds__(256)
qkv_tf32_kernel(const float* __restrict__ X,
                const float* __restrict__ Wq, const float* __restrict__ bq,
                const float* __restrict__ Wk, const float* __restrict__ bk,
                const float* __restrict__ Wv, const float* __restrict__ bv,
                float* __restrict__ q, float* __restrict__ k, float* __restrict__ v)
{
    const float* W; const float* bias; float* C;
    if (blockIdx.z == 0)      { W = Wq; bias = bq; C = q; }
    else if (blockIdx.z == 1) { W = Wk; bias = bk; C = k; }
    else                      { W = Wv; bias = bv; C = v; }
    gemm_body<128, 128, 32, false>(X, D_MODEL, W, D_MODEL, C, D_MODEL, bias, D_MODEL,
                                   blockIdx.y * 128, blockIdx.x * 128);
}

// ---------------------------------------------------------------------------
// Scores: writes e = exp(mask(QK/8)) into attn region, plus deterministic
// per-block partial row sums into g_part[z][row][bx].
// ---------------------------------------------------------------------------
template <int BM, int BN, int BK>
__global__ void __launch_bounds__(256)
scores_tf32_kernel(const float* __restrict__ Qm, const float* __restrict__ Km,
                   const unsigned char* __restrict__ mask, float* __restrict__ attn)
{
    constexpr int WTM = BM / 2, WTN = BN / 4;
    constexpr int MT = WTM / 16, NT = WTN / 8;
    __shared__ uint32_t As[BM][BK + 4];
    __shared__ uint32_t Bs[BN][BK + 4];   // [k_seq][d]
    __shared__ float sred[4][BM];

    const int z = blockIdx.z;
    const int b = z / N_HEADS;
    const int h = z % N_HEADS;
    const int tid = threadIdx.x, lane = tid & 31, wid = tid >> 5;
    const int wm = wid & 1, wn = wid >> 1;
    const int g = lane >> 2, t = lane & 3;

    const float* A  = Qm + (size_t)b * SEQ * D_MODEL + h * D_KH + (size_t)blockIdx.y * BM * D_MODEL;
    const float* Bp = Km + (size_t)b * SEQ * D_MODEL + h * D_KH + (size_t)blockIdx.x * BN * D_MODEL;
    float* C = attn + (size_t)z * SEQ * SEQ + (size_t)blockIdx.y * BM * SEQ + (size_t)blockIdx.x * BN;
    const unsigned char* Mp = mask + (size_t)b * SEQ * SEQ + (size_t)blockIdx.y * BM * SEQ + (size_t)blockIdx.x * BN;

    float c[MT][NT][4] = {};

    for (int kt = 0; kt < D_KH; kt += BK) {
#pragma unroll
        for (int l = 0; l < BM * BK / (256 * 4); l++) {
            int idx = tid + l * 256;
            int ar = idx / (BK / 4), ac = idx % (BK / 4);
            float4 v = *reinterpret_cast<const float4*>(&A[(size_t)ar * D_MODEL + kt + ac * 4]);
            As[ar][ac * 4 + 0] = f2tf32(v.x);
            As[ar][ac * 4 + 1] = f2tf32(v.y);
            As[ar][ac * 4 + 2] = f2tf32(v.z);
            As[ar][ac * 4 + 3] = f2tf32(v.w);
        }
#pragma unroll
        for (int l = 0; l < BN * BK / (256 * 4); l++) {
            int idx = tid + l * 256;
            int br = idx / (BK / 4), bc = idx % (BK / 4);
            float4 v = *reinterpret_cast<const float4*>(&Bp[(size_t)br * D_MODEL + kt + bc * 4]);
            Bs[br][bc * 4 + 0] = f2tf32(v.x);
            Bs[br][bc * 4 + 1] = f2tf32(v.y);
            Bs[br][bc * 4 + 2] = f2tf32(v.z);
            Bs[br][bc * 4 + 3] = f2tf32(v.w);
        }
        __syncthreads();
#pragma unroll
        for (int kk = 0; kk < BK / 8; kk++) {
            uint32_t a[MT][4], bfr[NT][2];
#pragma unroll
            for (int mt = 0; mt < MT; mt++) {
                int r = wm * WTM + mt * 16 + g;
                a[mt][0] = As[r][kk * 8 + t];
                a[mt][1] = As[r + 8][kk * 8 + t];
                a[mt][2] = As[r][kk * 8 + t + 4];
                a[mt][3] = As[r + 8][kk * 8 + t + 4];
            }
#pragma unroll
            for (int nt = 0; nt < NT; nt++) {
                int cc = wn * WTN + nt * 8 + g;
                bfr[nt][0] = Bs[cc][kk * 8 + t];
                bfr[nt][1] = Bs[cc][kk * 8 + t + 4];
            }
#pragma unroll
            for (int mt = 0; mt < MT; mt++)
#pragma unroll
                for (int nt = 0; nt < NT; nt++)
                    mma_tf32(c[mt][nt], a[mt][0], a[mt][1], a[mt][2], a[mt][3],
                             bfr[nt][0], bfr[nt][1]);
        }
        __syncthreads();
    }

    // Epilogue: e = exp(masked score); write e; accumulate partial row sums.
#pragma unroll
    for (int mt = 0; mt < MT; mt++) {
        int r = wm * WTM + mt * 16 + g;
        float s0 = 0.f, s1 = 0.f;
#pragma unroll
        for (int nt = 0; nt < NT; nt++) {
            int cc = wn * WTN + nt * 8 + 2 * t;
            float e00 = Mp[(size_t)r * SEQ + cc]           ? 0.f : __expf(c[mt][nt][0] * 0.125f);
            float e01 = Mp[(size_t)r * SEQ + cc + 1]       ? 0.f : __expf(c[mt][nt][1] * 0.125f);
            float e10 = Mp[(size_t)(r + 8) * SEQ + cc]     ? 0.f : __expf(c[mt][nt][2] * 0.125f);
            float e11 = Mp[(size_t)(r + 8) * SEQ + cc + 1] ? 0.f : __expf(c[mt][nt][3] * 0.125f);
            C[(size_t)r * SEQ + cc]           = e00;
            C[(size_t)r * SEQ + cc + 1]       = e01;
            C[(size_t)(r + 8) * SEQ + cc]     = e10;
            C[(size_t)(r + 8) * SEQ + cc + 1] = e11;
            s0 += e00 + e01;
            s1 += e10 + e11;
        }
        // reduce across the 4 t-lanes of this row group
        s0 += __shfl_xor_sync(0xffffffffu, s0, 1);
        s0 += __shfl_xor_sync(0xffffffffu, s0, 2);
        s1 += __shfl_xor_sync(0xffffffffu, s1, 1);
        s1 += __shfl_xor_sync(0xffffffffu, s1, 2);
        if (t == 0) {
            sred[wn][r]     = s0;
            sred[wn][r + 8] = s1;
        }
    }
    __syncthreads();
    if (tid < BM) {
        float s = sred[0][tid] + sred[1][tid] + sred[2][tid] + sred[3][tid];
        g_part[((size_t)z * SEQ + blockIdx.y * BM + tid) * NBX + blockIdx.x] = s;
    }
}

// ---------------------------------------------------------------------------
// Fused softmax + context, pipelined:
//   sinv[r] = 1 / sum of 16 partials (deterministic)
//   p = e * sinv  -> used as MMA A operand AND written in place (final attn).
// BM=128, BN=64, BK=32.
// ---------------------------------------------------------------------------
template <int BM, int BN, int BK>
__global__ void __launch_bounds__(256)
smctx_tf32_kernel(float* __restrict__ attn, const float* __restrict__ Vm,
                  float* __restrict__ C)
{
    extern __shared__ uint32_t smem[];
    constexpr int A_ST = BK + 4, B_ST = BN + 8;
    constexpr int WTM = BM / 2, WTN = BN / 4;
    constexpr int MT = WTM / 16, NT = WTN / 8;
    constexpr int LA = BM * BK / (256 * 4);
    constexpr int LB = BK * BN / (256 * 4);
    uint32_t* sA = smem;
    uint32_t* sB = smem + 2 * BM * A_ST;
    __shared__ float sinv[BM];

    const int z = blockIdx.z;
    const int b = z / N_HEADS;
    const int h = z % N_HEADS;
    const int tid = threadIdx.x, lane = tid & 31, wid = tid >> 5;
    const int wm = wid & 1, wn = wid >> 1;
    const int g = lane >> 2, t = lane & 3;

    float* Araw = attn + (size_t)z * SEQ * SEQ + (size_t)blockIdx.y * BM * SEQ;
    const float* Bp = Vm + (size_t)b * SEQ * D_MODEL + h * D_KH;
    float* Cp = C + (size_t)b * SEQ * D_MODEL + h * D_KH + (size_t)blockIdx.y * BM * D_MODEL;

    if (tid < BM) {
        const float* pp = &g_part[((size_t)z * SEQ + blockIdx.y * BM + tid) * NBX];
        float s = 0.f;
#pragma unroll
        for (int i = 0; i < NBX; i++) s += pp[i];
        sinv[tid] = 1.0f / s;
    }
    __syncthreads();

    float4 ra[LA], rb[LB];

#define SLOADG(kt)                                                             \
    {                                                                          \
        _Pragma("unroll")                                                      \
        for (int l = 0; l < LA; l++) {                                         \
            int idx = tid + l * 256;                                           \
            int ar = idx / (BK / 4), ac = idx % (BK / 4);                      \
            ra[l] = *reinterpret_cast<const float4*>(                          \
                &Araw[(size_t)ar * SEQ + (kt) * BK + ac * 4]);                 \
        }                                                                      \
        _Pragma("unroll")                                                      \
        for (int l = 0; l < LB; l++) {                                         \
            int idx = tid + l * 256;                                           \
            int br = idx / (BN / 4), bc = idx % (BN / 4);                      \
            rb[l] = *reinterpret_cast<const float4*>(                          \
                &Bp[(size_t)((kt) * BK + br) * D_MODEL + bc * 4]);             \
        }                                                                      \
    }

#define SSTORES(st, kt)                                                        \
    {                                                                          \
        uint32_t* pA = sA + (st) * BM * A_ST;                                  \
        uint32_t* pB = sB + (st) * BK * B_ST;                                  \
        _Pragma("unroll")                                                      \
        for (int l = 0; l < LA; l++) {                                         \
            int idx = tid + l * 256;                                           \
            int ar = idx / (BK / 4), ac = idx % (BK / 4);                      \
            float inv = sinv[ar];                                              \
            float4 p;                                                          \
            p.x = ra[l].x * inv; p.y = ra[l].y * inv;                          \
            p.z = ra[l].z * inv; p.w = ra[l].w * inv;                          \
            pA[ar * A_ST + ac * 4 + 0] = f2tf32(p.x);                          \
            pA[ar * A_ST + ac * 4 + 1] = f2tf32(p.y);                          \
            pA[ar * A_ST + ac * 4 + 2] = f2tf32(p.z);                          \
            pA[ar * A_ST + ac * 4 + 3] = f2tf32(p.w);                          \
            *reinterpret_cast<float4*>(                                        \
                &Araw[(size_t)ar * SEQ + (kt) * BK + ac * 4]) = p;             \
        }                                                                      \
        _Pragma("unroll")                                                      \
        for (int l = 0; l < LB; l++) {                                         \
            int idx = tid + l * 256;                                           \
            int br = idx / (BN / 4), bc = idx % (BN / 4);                      \
            pB[br * B_ST + bc * 4 + 0] = f2tf32(rb[l].x);                      \
            pB[br * B_ST + bc * 4 + 1] = f2tf32(rb[l].y);                      \
            pB[br * B_ST + bc * 4 + 2] = f2tf32(rb[l].z);                      \
            pB[br * B_ST + bc * 4 + 3] = f2tf32(rb[l].w);                      \
        }                                                                      \
    }

    float c[MT][NT][4] = {};
    const int nk = SEQ / BK;

    SLOADG(0);
    SSTORES(0, 0);

    for (int kt = 1; kt <= nk; kt++) {
        __syncthreads();
        if (kt < nk) SLOADG(kt);
        const uint32_t* pA = sA + ((kt - 1) & 1) * BM * A_ST;
        const uint32_t* pB = sB + ((kt - 1) & 1) * BK * B_ST;
#pragma unroll
        for (int kk = 0; kk < BK / 8; kk++) {
            uint32_t a[MT][4], bfr[NT][2];
#pragma unroll
            for (int mt = 0; mt < MT; mt++) {
                int r = wm * WTM + mt * 16 + g;
                a[mt][0] = pA[r * A_ST + kk * 8 + t];
                a[mt][1] = pA[(r + 8) * A_ST + kk * 8 + t];
                a[mt][2] = pA[r * A_ST + kk * 8 + t + 4];
                a[mt][3] = pA[(r + 8) * A_ST + kk * 8 + t + 4];
            }
#pragma unroll
            for (int nt = 0; nt < NT; nt++) {
                int cc = wn * WTN + nt * 8 + g;
                bfr[nt][0] = pB[(kk * 8 + t) * B_ST + cc];
                bfr[nt][1] = pB[(kk * 8 + t + 4) * B_ST + cc];
            }
#pragma unroll
            for (int mt = 0; mt < MT; mt++)
#pragma unroll
                for (int nt = 0; nt < NT; nt++)
                    mma_tf32(c[mt][nt], a[mt][0], a[mt][1], a[mt][2], a[mt][3],
                             bfr[nt][0], bfr[nt][1]);
        }
        if (kt < nk) SSTORES(kt & 1, kt);
    }
#undef SLOADG
#undef SSTORES

#pragma unroll
    for (int mt = 0; mt < MT; mt++) {
        int r = wm * WTM + mt * 16 + g;
#pragma unroll
        for (int nt = 0; nt < NT; nt++) {
            int cc = wn * WTN + nt * 8 + 2 * t;
            Cp[(size_t)r * D_MODEL + cc]           = c[mt][nt][0];
            Cp[(size_t)r * D_MODEL + cc + 1]       = c[mt][nt][1];
            Cp[(size_t)(r + 8) * D_MODEL + cc]     = c[mt][nt][2];
            Cp[(size_t)(r + 8) * D_MODEL + cc + 1] = c[mt][nt][3];
        }
    }
}

// ---------------------------------------------------------------------------
// LayerNorm
// ---------------------------------------------------------------------------
__device__ __forceinline__ float warp_sum(float v) {
#pragma unroll
    for (int o = 16; o; o >>= 1) v += __shfl_xor_sync(0xffffffffu, v, o);
    return v;
}

__global__ void __launch_bounds__(256)
ln_kernel(const float* __restrict__ x, const float* __restrict__ resid,
          const float* __restrict__ gamma, const float* __restrict__ beta,
          float* __restrict__ out)
{
    __shared__ float s_s[8];
    __shared__ float s_ss[8];
    const int row = blockIdx.x;
    const int tid = threadIdx.x;
    const int lane = tid & 31;
    const int wid = tid >> 5;
    const float* xr = x + (size_t)row * D_MODEL;
    const float* rr = resid + (size_t)row * D_MODEL;

    float v[3];
    float s = 0.f, ss = 0.f;
#pragma unroll
    for (int i = 0; i < 3; i++) {
        int c = tid + i * 256;
        v[i] = xr[c] + rr[c];
        s  += v[i];
        ss += v[i] * v[i];
    }
    s = warp_sum(s);
    ss = warp_sum(ss);
    if (lane == 0) { s_s[wid] = s; s_ss[wid] = ss; }
    __syncthreads();
    float ts = 0.f, tss = 0.f;
#pragma unroll
    for (int i = 0; i < 8; i++) { ts += s_s[i]; tss += s_ss[i]; }
    const float mean = ts * (1.0f / D_MODEL);
    const float var  = tss * (1.0f / D_MODEL) - mean * mean;
    const float inv  = rsqrtf(var + 1e-5f);

#pragma unroll
    for (int i = 0; i < 3; i++) {
        int c = tid + i * 256;
        out[(size_t)row * D_MODEL + c] = (v[i] - mean) * inv * gamma[c] + beta[c];
    }
}

// ---------------------------------------------------------------------------
// Launch
// ---------------------------------------------------------------------------
extern "C" void kernel_launch(void* const* d_in, const int* in_sizes, int n_in,
                              void* d_out, int out_size)
{
    const float* X              = (const float*)d_in[0];
    const unsigned char* mask   = (const unsigned char*)d_in[1];
    const float* Wq = (const float*)d_in[2];
    const float* bq = (const float*)d_in[3];
    const float* Wk = (const float*)d_in[4];
    const float* bk = (const float*)d_in[5];
    const float* Wv = (const float*)d_in[6];
    const float* bv = (const float*)d_in[7];
    const float* Wo = (const float*)d_in[8];
    const float* bo = (const float*)d_in[9];
    const float* ln1g = (const float*)d_in[10];
    const float* ln1b = (const float*)d_in[11];
    const float* W1 = (const float*)d_in[12];
    const float* b1 = (const float*)d_in[13];
    const float* W2 = (const float*)d_in[14];
    const float* b2 = (const float*)d_in[15];
    const float* ln2g = (const float*)d_in[16];
    const float* ln2b = (const float*)d_in[17];

    float* out  = (float*)d_out;
    float* attn = out + OUT_ELEMS;

    float *q, *k, *v, *ctx, *t1, *ao, *ffn, *t2;
    cudaGetSymbolAddress((void**)&q,   g_q);
    cudaGetSymbolAddress((void**)&k,   g_k);
    cudaGetSymbolAddress((void**)&v,   g_v);
    cudaGetSymbolAddress((void**)&ctx, g_ctx);
    cudaGetSymbolAddress((void**)&t1,  g_t1);
    cudaGetSymbolAddress((void**)&ao,  g_ao);
    cudaGetSymbolAddress((void**)&ffn, g_ffn);
    cudaGetSymbolAddress((void**)&t2,  g_t2);

    // Dynamic smem sizes (2-stage double buffer)
    const int smem_gemm  = (2 * 128 * 36 + 2 * 32 * 136) * 4;   // 71680
    const int smem_smctx = (2 * 128 * 36 + 2 * 32 * 72) * 4;    // 55296

    cudaFuncSetAttribute(gemm_tf32_kernel<128, 128, 32, false>,
                         cudaFuncAttributeMaxDynamicSharedMemorySize, smem_gemm);
    cudaFuncSetAttribute(gemm_tf32_kernel<128, 128, 32, true>,
                         cudaFuncAttributeMaxDynamicSharedMemorySize, smem_gemm);
    cudaFuncSetAttribute(qkv_tf32_kernel,
                         cudaFuncAttributeMaxDynamicSharedMemorySize, smem_gemm);
    cudaFuncSetAttribute(smctx_tf32_kernel<128, 64, 32>,
                         cudaFuncAttributeMaxDynamicSharedMemorySize, smem_smctx);

    // Fused QKV projections
    qkv_tf32_kernel<<<dim3(D_MODEL / 128, ROWS / 128, 3), 256, smem_gemm>>>(
        X, Wq, bq, Wk, bk, Wv, bv, q, k, v);

    // Scores -> e values + partial row sums
    scores_tf32_kernel<128, 128, 32><<<dim3(NBX, SEQ / 128, NZ), 256>>>(
        q, k, mask, attn);

    // Fused softmax + context (writes normalized probs in place)
    smctx_tf32_kernel<128, 64, 32><<<dim3(1, SEQ / 128, NZ), 256, smem_smctx>>>(
        attn, v, ctx);

    // Output projection + LN1
    dim3 g768(D_MODEL / 128, ROWS / 128);
    gemm_tf32_kernel<128, 128, 32, false><<<g768, 256, smem_gemm>>>(
        ctx, D_MODEL, Wo, D_MODEL, t1, D_MODEL, bo, D_MODEL);
    ln_kernel<<<ROWS, 256>>>(t1, X, ln1g, ln1b, ao);

    // FFN
    gemm_tf32_kernel<128, 128, 32, true ><<<dim3(D_FF / 128, ROWS / 128), 256, smem_gemm>>>(
        ao, D_MODEL, W1, D_FF, ffn, D_FF, b1, D_MODEL);
    gemm_tf32_kernel<128, 128, 32, false><<<g768, 256, smem_gemm>>>(
        ffn, D_FF, W2, D_MODEL, t2, D_MODEL, b2, D_FF);

    ln_kernel<<<ROWS, 256>>>(t2, ao, ln2g, ln2b, out);
}

// round 7
// speedup vs baseline: 2.7676x; 1.0741x over previous
#include <cuda_runtime.h>
#include <math.h>
#include <stdint.h>

#define D_MODEL 768
#define N_HEADS 12
#define D_FF    3072
#define D_KH    64
#define BATCH   2
#define SEQ     2048
#define ROWS    (BATCH * SEQ)
#define OUT_ELEMS ((size_t)ROWS * D_MODEL)
#define NZ (BATCH * N_HEADS)
#define NBX (SEQ / 128)

// Scratch
__device__ float g_q[ROWS * D_MODEL];
__device__ float g_k[ROWS * D_MODEL];
__device__ float g_v[ROWS * D_MODEL];
__device__ float g_ctx[ROWS * D_MODEL];
__device__ float g_t1[ROWS * D_MODEL];
__device__ float g_ao[ROWS * D_MODEL];
__device__ float g_aor[ROWS * D_MODEL];
__device__ float g_ffn[ROWS * D_FF];
__device__ float g_t2[ROWS * D_MODEL];
__device__ float g_part[(size_t)NZ * SEQ * NBX];
// tf32-pre-rounded copies
__device__ float g_xr[ROWS * D_MODEL];
__device__ float g_wq[D_MODEL * D_MODEL];
__device__ float g_wk[D_MODEL * D_MODEL];
__device__ float g_wv[D_MODEL * D_MODEL];
__device__ float g_wo[D_MODEL * D_MODEL];
__device__ float g_w1[D_MODEL * D_FF];
__device__ float g_w2[D_FF * D_MODEL];

// ---------------------------------------------------------------------------
// Helpers
// ---------------------------------------------------------------------------
__device__ __forceinline__ uint32_t f2tf32(float f) {
    uint32_t r;
    asm("cvt.rna.tf32.f32 %0, %1;" : "=r"(r) : "f"(f));
    return r;
}
__device__ __forceinline__ float roundtf(float f) { return __uint_as_float(f2tf32(f)); }

__device__ __forceinline__ void mma_tf32(float* c,
                                         uint32_t a0, uint32_t a1, uint32_t a2, uint32_t a3,
                                         uint32_t b0, uint32_t b1) {
    asm("mma.sync.aligned.m16n8k8.row.col.f32.tf32.tf32.f32 "
        "{%0,%1,%2,%3}, {%4,%5,%6,%7}, {%8,%9}, {%0,%1,%2,%3};"
        : "+f"(c[0]), "+f"(c[1]), "+f"(c[2]), "+f"(c[3])
        : "r"(a0), "r"(a1), "r"(a2), "r"(a3), "r"(b0), "r"(b1));
}

__device__ __forceinline__ void cpa16(uint32_t s, const float* g) {
    asm volatile("cp.async.cg.shared.global [%0], [%1], 16;" :: "r"(s), "l"(g));
}
#define CP_COMMIT() asm volatile("cp.async.commit_group;")
#define CP_WAIT1()  asm volatile("cp.async.wait_group 1;")

__device__ __forceinline__ float warp_sum(float v) {
#pragma unroll
    for (int o = 16; o; o >>= 1) v += __shfl_xor_sync(0xffffffffu, v, o);
    return v;
}

// ---------------------------------------------------------------------------
// Pre-round kernel: 7 segments, each in[i] -> out[i] rounded to tf32.
// ---------------------------------------------------------------------------
struct RoundArgs {
    const float* in[7];
    float* out[7];
    int n[7];
};
__global__ void __launch_bounds__(256)
round7_kernel(RoundArgs a)
{
    int seg = blockIdx.y;
    int base = (blockIdx.x * 256 + threadIdx.x) * 4;
    if (base >= a.n[seg]) return;
    float4 v = *reinterpret_cast<const float4*>(a.in[seg] + base);
    v.x = roundtf(v.x); v.y = roundtf(v.y);
    v.z = roundtf(v.z); v.w = roundtf(v.w);
    *reinterpret_cast<float4*>(a.out[seg] + base) = v;
}

// ---------------------------------------------------------------------------
// cp.async 3-stage pipelined TF32 GEMM. Inputs MUST be tf32-pre-rounded.
// C = A[M,K](rm) @ B[K,N](rm) + bias. BM=128 BN=128 BK=32, 256 threads.
// ---------------------------------------------------------------------------
template <int BM, int BN, int BK, bool RELU, bool ROUND>
__device__ __forceinline__ void gemm_cp_body(const float* __restrict__ A, int lda,
                                             const float* __restrict__ B, int ldb,
                                             float* __restrict__ C, int ldc,
                                             const float* __restrict__ bias, int K,
                                             int row0, int col0)
{
    extern __shared__ float smem[];
    constexpr int A_ST = BK + 4, B_ST = BN + 8;
    constexpr int SA_W = BM * A_ST, SB_W = BK * B_ST;
    constexpr int STAGE_W = SA_W + SB_W;
    constexpr int WTM = BM / 2, WTN = BN / 4;
    constexpr int MT = WTM / 16, NT = WTN / 8;
    constexpr int LA = BM * BK / (256 * 4);
    constexpr int LB = BK * BN / (256 * 4);

    const int tid = threadIdx.x, lane = tid & 31, wid = tid >> 5;
    const int wm = wid & 1, wn = wid >> 1;
    const int g = lane >> 2, t = lane & 3;

    A += (size_t)row0 * lda;
    B += col0;

    const uint32_t sbase = (uint32_t)__cvta_generic_to_shared(smem);

    // Per-thread load coordinates
    int aar[LA], aac[LA], bbr[LB], bbc[LB];
#pragma unroll
    for (int l = 0; l < LA; l++) {
        int idx = tid + l * 256;
        aar[l] = idx / (BK / 4);
        aac[l] = idx % (BK / 4);
    }
#pragma unroll
    for (int l = 0; l < LB; l++) {
        int idx = tid + l * 256;
        bbr[l] = idx / (BN / 4);
        bbc[l] = idx % (BN / 4);
    }

#define ISSUE(kt, st)                                                          \
    {                                                                          \
        uint32_t sa = sbase + (st) * STAGE_W * 4;                              \
        uint32_t sb = sa + SA_W * 4;                                           \
        _Pragma("unroll")                                                      \
        for (int l = 0; l < LA; l++)                                           \
            cpa16(sa + (aar[l] * A_ST + aac[l] * 4) * 4,                       \
                  &A[(size_t)aar[l] * lda + (kt) * BK + aac[l] * 4]);          \
        _Pragma("unroll")                                                      \
        for (int l = 0; l < LB; l++)                                           \
            cpa16(sb + (bbr[l] * B_ST + bbc[l] * 4) * 4,                       \
                  &B[(size_t)((kt) * BK + bbr[l]) * ldb + bbc[l] * 4]);        \
    }

    float c[MT][NT][4] = {};
    const int nk = K / BK;

    ISSUE(0, 0); CP_COMMIT();
    ISSUE(1, 1); CP_COMMIT();

    for (int kt = 0; kt < nk; kt++) {
        CP_WAIT1();
        __syncthreads();
        if (kt + 2 < nk) ISSUE(kt + 2, (kt + 2) % 3);
        CP_COMMIT();

        const uint32_t* pA = reinterpret_cast<const uint32_t*>(smem) + (kt % 3) * STAGE_W;
        const uint32_t* pB = pA + SA_W;
#pragma unroll
        for (int kk = 0; kk < BK / 8; kk++) {
            uint32_t a[MT][4], b[NT][2];
#pragma unroll
            for (int mt = 0; mt < MT; mt++) {
                int r = wm * WTM + mt * 16 + g;
                a[mt][0] = pA[r * A_ST + kk * 8 + t];
                a[mt][1] = pA[(r + 8) * A_ST + kk * 8 + t];
                a[mt][2] = pA[r * A_ST + kk * 8 + t + 4];
                a[mt][3] = pA[(r + 8) * A_ST + kk * 8 + t + 4];
            }
#pragma unroll
            for (int nt = 0; nt < NT; nt++) {
                int cc = wn * WTN + nt * 8 + g;
                b[nt][0] = pB[(kk * 8 + t) * B_ST + cc];
                b[nt][1] = pB[(kk * 8 + t + 4) * B_ST + cc];
            }
#pragma unroll
            for (int mt = 0; mt < MT; mt++)
#pragma unroll
                for (int nt = 0; nt < NT; nt++)
                    mma_tf32(c[mt][nt], a[mt][0], a[mt][1], a[mt][2], a[mt][3],
                             b[nt][0], b[nt][1]);
        }
    }
#undef ISSUE

    C += (size_t)row0 * ldc + col0;
#pragma unroll
    for (int mt = 0; mt < MT; mt++) {
        int r = wm * WTM + mt * 16 + g;
#pragma unroll
        for (int nt = 0; nt < NT; nt++) {
            int cc = wn * WTN + nt * 8 + 2 * t;
            float b0 = bias[col0 + cc], b1 = bias[col0 + cc + 1];
            float v00 = c[mt][nt][0] + b0, v01 = c[mt][nt][1] + b1;
            float v10 = c[mt][nt][2] + b0, v11 = c[mt][nt][3] + b1;
            if (RELU) {
                v00 = fmaxf(v00, 0.f); v01 = fmaxf(v01, 0.f);
                v10 = fmaxf(v10, 0.f); v11 = fmaxf(v11, 0.f);
            }
            if (ROUND) {
                v00 = roundtf(v00); v01 = roundtf(v01);
                v10 = roundtf(v10); v11 = roundtf(v11);
            }
            C[(size_t)r * ldc + cc]           = v00;
            C[(size_t)r * ldc + cc + 1]       = v01;
            C[(size_t)(r + 8) * ldc + cc]     = v10;
            C[(size_t)(r + 8) * ldc + cc + 1] = v11;
        }
    }
}

template <int BM, int BN, int BK, bool RELU, bool ROUND>
__global__ void __launch_bounds__(256)
gemm_cp_kernel(const float* __restrict__ A, int lda,
               const float* __restrict__ B, int ldb,
               float* __restrict__ C, int ldc,
               const float* __restrict__ bias, int K)
{
    gemm_cp_body<BM, BN, BK, RELU, ROUND>(A, lda, B, ldb, C, ldc, bias, K,
                                          blockIdx.y * BM, blockIdx.x * BN);
}

__global__ void __launch_bounds__(256)
qkv_cp_kernel(const float* __restrict__ Xr,
              const float* __restrict__ Wq, const float* __restrict__ bq,
              const float* __restrict__ Wk, const float* __restrict__ bk,
              const float* __restrict__ Wv, const float* __restrict__ bv,
              float* __restrict__ q, float* __restrict__ k, float* __restrict__ v)
{
    const float* W; const float* bias; float* C;
    if (blockIdx.z == 0)      { W = Wq; bias = bq; C = q; }
    else if (blockIdx.z == 1) { W = Wk; bias = bk; C = k; }
    else                      { W = Wv; bias = bv; C = v; }
    gemm_cp_body<128, 128, 32, false, true>(Xr, D_MODEL, W, D_MODEL, C, D_MODEL, bias,
                                            D_MODEL, blockIdx.y * 128, blockIdx.x * 128);
}

// ---------------------------------------------------------------------------
// Scores: q/k pre-rounded; writes e = exp(mask(QK/8)) + partial row sums.
// ---------------------------------------------------------------------------
template <int BM, int BN, int BK>
__global__ void __launch_bounds__(256)
scores_tf32_kernel(const float* __restrict__ Qm, const float* __restrict__ Km,
                   const unsigned char* __restrict__ mask, float* __restrict__ attn)
{
    constexpr int WTM = BM / 2, WTN = BN / 4;
    constexpr int MT = WTM / 16, NT = WTN / 8;
    __shared__ float As[BM][BK + 4];
    __shared__ float Bs[BN][BK + 4];
    __shared__ float sred[4][BM];

    const int z = blockIdx.z;
    const int b = z / N_HEADS;
    const int h = z % N_HEADS;
    const int tid = threadIdx.x, lane = tid & 31, wid = tid >> 5;
    const int wm = wid & 1, wn = wid >> 1;
    const int g = lane >> 2, t = lane & 3;

    const float* A  = Qm + (size_t)b * SEQ * D_MODEL + h * D_KH + (size_t)blockIdx.y * BM * D_MODEL;
    const float* Bp = Km + (size_t)b * SEQ * D_MODEL + h * D_KH + (size_t)blockIdx.x * BN * D_MODEL;
    float* C = attn + (size_t)z * SEQ * SEQ + (size_t)blockIdx.y * BM * SEQ + (size_t)blockIdx.x * BN;
    const unsigned char* Mp = mask + (size_t)b * SEQ * SEQ + (size_t)blockIdx.y * BM * SEQ + (size_t)blockIdx.x * BN;

    float c[MT][NT][4] = {};

    for (int kt = 0; kt < D_KH; kt += BK) {
#pragma unroll
        for (int l = 0; l < BM * BK / (256 * 4); l++) {
            int idx = tid + l * 256;
            int ar = idx / (BK / 4), ac = idx % (BK / 4);
            *reinterpret_cast<float4*>(&As[ar][ac * 4]) =
                *reinterpret_cast<const float4*>(&A[(size_t)ar * D_MODEL + kt + ac * 4]);
        }
#pragma unroll
        for (int l = 0; l < BN * BK / (256 * 4); l++) {
            int idx = tid + l * 256;
            int br = idx / (BK / 4), bc = idx % (BK / 4);
            *reinterpret_cast<float4*>(&Bs[br][bc * 4]) =
                *reinterpret_cast<const float4*>(&Bp[(size_t)br * D_MODEL + kt + bc * 4]);
        }
        __syncthreads();
        const uint32_t* uA = reinterpret_cast<const uint32_t*>(&As[0][0]);
        const uint32_t* uB = reinterpret_cast<const uint32_t*>(&Bs[0][0]);
#pragma unroll
        for (int kk = 0; kk < BK / 8; kk++) {
            uint32_t a[MT][4], bfr[NT][2];
#pragma unroll
            for (int mt = 0; mt < MT; mt++) {
                int r = wm * WTM + mt * 16 + g;
                a[mt][0] = uA[r * (BK + 4) + kk * 8 + t];
                a[mt][1] = uA[(r + 8) * (BK + 4) + kk * 8 + t];
                a[mt][2] = uA[r * (BK + 4) + kk * 8 + t + 4];
                a[mt][3] = uA[(r + 8) * (BK + 4) + kk * 8 + t + 4];
            }
#pragma unroll
            for (int nt = 0; nt < NT; nt++) {
                int cc = wn * WTN + nt * 8 + g;
                bfr[nt][0] = uB[cc * (BK + 4) + kk * 8 + t];
                bfr[nt][1] = uB[cc * (BK + 4) + kk * 8 + t + 4];
            }
#pragma unroll
            for (int mt = 0; mt < MT; mt++)
#pragma unroll
                for (int nt = 0; nt < NT; nt++)
                    mma_tf32(c[mt][nt], a[mt][0], a[mt][1], a[mt][2], a[mt][3],
                             bfr[nt][0], bfr[nt][1]);
        }
        __syncthreads();
    }

#pragma unroll
    for (int mt = 0; mt < MT; mt++) {
        int r = wm * WTM + mt * 16 + g;
        float s0 = 0.f, s1 = 0.f;
#pragma unroll
        for (int nt = 0; nt < NT; nt++) {
            int cc = wn * WTN + nt * 8 + 2 * t;
            float e00 = Mp[(size_t)r * SEQ + cc]           ? 0.f : __expf(c[mt][nt][0] * 0.125f);
            float e01 = Mp[(size_t)r * SEQ + cc + 1]       ? 0.f : __expf(c[mt][nt][1] * 0.125f);
            float e10 = Mp[(size_t)(r + 8) * SEQ + cc]     ? 0.f : __expf(c[mt][nt][2] * 0.125f);
            float e11 = Mp[(size_t)(r + 8) * SEQ + cc + 1] ? 0.f : __expf(c[mt][nt][3] * 0.125f);
            C[(size_t)r * SEQ + cc]           = e00;
            C[(size_t)r * SEQ + cc + 1]       = e01;
            C[(size_t)(r + 8) * SEQ + cc]     = e10;
            C[(size_t)(r + 8) * SEQ + cc + 1] = e11;
            s0 += e00 + e01;
            s1 += e10 + e11;
        }
        s0 += __shfl_xor_sync(0xffffffffu, s0, 1);
        s0 += __shfl_xor_sync(0xffffffffu, s0, 2);
        s1 += __shfl_xor_sync(0xffffffffu, s1, 1);
        s1 += __shfl_xor_sync(0xffffffffu, s1, 2);
        if (t == 0) {
            sred[wn][r]     = s0;
            sred[wn][r + 8] = s1;
        }
    }
    __syncthreads();
    if (tid < BM) {
        float s = sred[0][tid] + sred[1][tid] + sred[2][tid] + sred[3][tid];
        g_part[((size_t)z * SEQ + blockIdx.y * BM + tid) * NBX + blockIdx.x] = s;
    }
}

// ---------------------------------------------------------------------------
// Fused softmax + context: V pre-rounded; ctx output rounded (feeds Wo GEMM).
// ---------------------------------------------------------------------------
template <int BM, int BN, int BK>
__global__ void __launch_bounds__(256)
smctx_tf32_kernel(float* __restrict__ attn, const float* __restrict__ Vm,
                  float* __restrict__ C)
{
    extern __shared__ float smemf[];
    constexpr int A_ST = BK + 4, B_ST = BN + 8;
    constexpr int WTM = BM / 2, WTN = BN / 4;
    constexpr int MT = WTM / 16, NT = WTN / 8;
    constexpr int LA = BM * BK / (256 * 4);
    constexpr int LB = BK * BN / (256 * 4);
    uint32_t* sA = reinterpret_cast<uint32_t*>(smemf);
    float*    sB = smemf + 2 * BM * A_ST;
    __shared__ float sinv[BM];

    const int z = blockIdx.z;
    const int b = z / N_HEADS;
    const int h = z % N_HEADS;
    const int tid = threadIdx.x, lane = tid & 31, wid = tid >> 5;
    const int wm = wid & 1, wn = wid >> 1;
    const int g = lane >> 2, t = lane & 3;

    float* Araw = attn + (size_t)z * SEQ * SEQ + (size_t)blockIdx.y * BM * SEQ;
    const float* Bp = Vm + (size_t)b * SEQ * D_MODEL + h * D_KH;
    float* Cp = C + (size_t)b * SEQ * D_MODEL + h * D_KH + (size_t)blockIdx.y * BM * D_MODEL;

    if (tid < BM) {
        const float* pp = &g_part[((size_t)z * SEQ + blockIdx.y * BM + tid) * NBX];
        float s = 0.f;
#pragma unroll
        for (int i = 0; i < NBX; i++) s += pp[i];
        sinv[tid] = 1.0f / s;
    }
    __syncthreads();

    float4 ra[LA], rb[LB];

#define SLOADG(kt)                                                             \
    {                                                                          \
        _Pragma("unroll")                                                      \
        for (int l = 0; l < LA; l++) {                                         \
            int idx = tid + l * 256;                                           \
            int ar = idx / (BK / 4), ac = idx % (BK / 4);                      \
            ra[l] = *reinterpret_cast<const float4*>(                          \
                &Araw[(size_t)ar * SEQ + (kt) * BK + ac * 4]);                 \
        }                                                                      \
        _Pragma("unroll")                                                      \
        for (int l = 0; l < LB; l++) {                                         \
            int idx = tid + l * 256;                                           \
            int br = idx / (BN / 4), bc = idx % (BN / 4);                      \
            rb[l] = *reinterpret_cast<const float4*>(                          \
                &Bp[(size_t)((kt) * BK + br) * D_MODEL + bc * 4]);             \
        }                                                                      \
    }

#define SSTORES(st, kt)                                                        \
    {                                                                          \
        uint32_t* pA = sA + (st) * BM * A_ST;                                  \
        float*    pB = sB + (st) * BK * B_ST;                                  \
        _Pragma("unroll")                                                      \
        for (int l = 0; l < LA; l++) {                                         \
            int idx = tid + l * 256;                                           \
            int ar = idx / (BK / 4), ac = idx % (BK / 4);                      \
            float inv = sinv[ar];                                              \
            float4 p;                                                          \
            p.x = ra[l].x * inv; p.y = ra[l].y * inv;                          \
            p.z = ra[l].z * inv; p.w = ra[l].w * inv;                          \
            pA[ar * A_ST + ac * 4 + 0] = f2tf32(p.x);                          \
            pA[ar * A_ST + ac * 4 + 1] = f2tf32(p.y);                          \
            pA[ar * A_ST + ac * 4 + 2] = f2tf32(p.z);                          \
            pA[ar * A_ST + ac * 4 + 3] = f2tf32(p.w);                          \
            *reinterpret_cast<float4*>(                                        \
                &Araw[(size_t)ar * SEQ + (kt) * BK + ac * 4]) = p;             \
        }                                                                      \
        _Pragma("unroll")                                                      \
        for (int l = 0; l < LB; l++) {                                         \
            int idx = tid + l * 256;                                           \
            int br = idx / (BN / 4), bc = idx % (BN / 4);                      \
            *reinterpret_cast<float4*>(&pB[br * B_ST + bc * 4]) = rb[l];       \
        }                                                                      \
    }

    float c[MT][NT][4] = {};
    const int nk = SEQ / BK;

    SLOADG(0);
    SSTORES(0, 0);

    for (int kt = 1; kt <= nk; kt++) {
        __syncthreads();
        if (kt < nk) SLOADG(kt);
        const uint32_t* pA = sA + ((kt - 1) & 1) * BM * A_ST;
        const uint32_t* pB = reinterpret_cast<const uint32_t*>(sB + ((kt - 1) & 1) * BK * B_ST);
#pragma unroll
        for (int kk = 0; kk < BK / 8; kk++) {
            uint32_t a[MT][4], bfr[NT][2];
#pragma unroll
            for (int mt = 0; mt < MT; mt++) {
                int r = wm * WTM + mt * 16 + g;
                a[mt][0] = pA[r * A_ST + kk * 8 + t];
                a[mt][1] = pA[(r + 8) * A_ST + kk * 8 + t];
                a[mt][2] = pA[r * A_ST + kk * 8 + t + 4];
                a[mt][3] = pA[(r + 8) * A_ST + kk * 8 + t + 4];
            }
#pragma unroll
            for (int nt = 0; nt < NT; nt++) {
                int cc = wn * WTN + nt * 8 + g;
                bfr[nt][0] = pB[(kk * 8 + t) * B_ST + cc];
                bfr[nt][1] = pB[(kk * 8 + t + 4) * B_ST + cc];
            }
#pragma unroll
            for (int mt = 0; mt < MT; mt++)
#pragma unroll
                for (int nt = 0; nt < NT; nt++)
                    mma_tf32(c[mt][nt], a[mt][0], a[mt][1], a[mt][2], a[mt][3],
                             bfr[nt][0], bfr[nt][1]);
        }
        if (kt < nk) SSTORES(kt & 1, kt);
    }
#undef SLOADG
#undef SSTORES

#pragma unroll
    for (int mt = 0; mt < MT; mt++) {
        int r = wm * WTM + mt * 16 + g;
#pragma unroll
        for (int nt = 0; nt < NT; nt++) {
            int cc = wn * WTN + nt * 8 + 2 * t;
            Cp[(size_t)r * D_MODEL + cc]           = roundtf(c[mt][nt][0]);
            Cp[(size_t)r * D_MODEL + cc + 1]       = roundtf(c[mt][nt][1]);
            Cp[(size_t)(r + 8) * D_MODEL + cc]     = roundtf(c[mt][nt][2]);
            Cp[(size_t)(r + 8) * D_MODEL + cc + 1] = roundtf(c[mt][nt][3]);
        }
    }
}

// ---------------------------------------------------------------------------
// LayerNorm: out = LN(x + resid); optional tf32-rounded second output.
// ---------------------------------------------------------------------------
__global__ void __launch_bounds__(256)
ln_kernel(const float* __restrict__ x, const float* __restrict__ resid,
          const float* __restrict__ gamma, const float* __restrict__ beta,
          float* __restrict__ out, float* __restrict__ out_r)
{
    __shared__ float s_s[8];
    __shared__ float s_ss[8];
    const int row = blockIdx.x;
    const int tid = threadIdx.x;
    const int lane = tid & 31;
    const int wid = tid >> 5;
    const float* xr = x + (size_t)row * D_MODEL;
    const float* rr = resid + (size_t)row * D_MODEL;

    float v[3];
    float s = 0.f, ss = 0.f;
#pragma unroll
    for (int i = 0; i < 3; i++) {
        int c = tid + i * 256;
        v[i] = xr[c] + rr[c];
        s  += v[i];
        ss += v[i] * v[i];
    }
    s = warp_sum(s);
    ss = warp_sum(ss);
    if (lane == 0) { s_s[wid] = s; s_ss[wid] = ss; }
    __syncthreads();
    float ts = 0.f, tss = 0.f;
#pragma unroll
    for (int i = 0; i < 8; i++) { ts += s_s[i]; tss += s_ss[i]; }
    const float mean = ts * (1.0f / D_MODEL);
    const float var  = tss * (1.0f / D_MODEL) - mean * mean;
    const float inv  = rsqrtf(var + 1e-5f);

#pragma unroll
    for (int i = 0; i < 3; i++) {
        int c = tid + i * 256;
        float o = (v[i] - mean) * inv * gamma[c] + beta[c];
        out[(size_t)row * D_MODEL + c] = o;
        if (out_r) out_r[(size_t)row * D_MODEL + c] = roundtf(o);
    }
}

// ---------------------------------------------------------------------------
// Launch
// ---------------------------------------------------------------------------
extern "C" void kernel_launch(void* const* d_in, const int* in_sizes, int n_in,
                              void* d_out, int out_size)
{
    const float* X              = (const float*)d_in[0];
    const unsigned char* mask   = (const unsigned char*)d_in[1];
    const float* Wq = (const float*)d_in[2];
    const float* bq = (const float*)d_in[3];
    const float* Wk = (const float*)d_in[4];
    const float* bk = (const float*)d_in[5];
    const float* Wv = (const float*)d_in[6];
    const float* bv = (const float*)d_in[7];
    const float* Wo = (const float*)d_in[8];
    const float* bo = (const float*)d_in[9];
    const float* ln1g = (const float*)d_in[10];
    const float* ln1b = (const float*)d_in[11];
    const float* W1 = (const float*)d_in[12];
    const float* b1 = (const float*)d_in[13];
    const float* W2 = (const float*)d_in[14];
    const float* b2 = (const float*)d_in[15];
    const float* ln2g = (const float*)d_in[16];
    const float* ln2b = (const float*)d_in[17];

    float* out  = (float*)d_out;
    float* attn = out + OUT_ELEMS;

    float *q, *k, *v, *ctx, *t1, *ao, *aor, *ffn, *t2;
    float *xr, *wq, *wk, *wv, *wo, *w1, *w2;
    cudaGetSymbolAddress((void**)&q,   g_q);
    cudaGetSymbolAddress((void**)&k,   g_k);
    cudaGetSymbolAddress((void**)&v,   g_v);
    cudaGetSymbolAddress((void**)&ctx, g_ctx);
    cudaGetSymbolAddress((void**)&t1,  g_t1);
    cudaGetSymbolAddress((void**)&ao,  g_ao);
    cudaGetSymbolAddress((void**)&aor, g_aor);
    cudaGetSymbolAddress((void**)&ffn, g_ffn);
    cudaGetSymbolAddress((void**)&t2,  g_t2);
    cudaGetSymbolAddress((void**)&xr,  g_xr);
    cudaGetSymbolAddress((void**)&wq,  g_wq);
    cudaGetSymbolAddress((void**)&wk,  g_wk);
    cudaGetSymbolAddress((void**)&wv,  g_wv);
    cudaGetSymbolAddress((void**)&wo,  g_wo);
    cudaGetSymbolAddress((void**)&w1,  g_w1);
    cudaGetSymbolAddress((void**)&w2,  g_w2);

    // Pre-round inputs/weights to tf32
    RoundArgs ra;
    ra.in[0] = X;  ra.out[0] = xr; ra.n[0] = ROWS * D_MODEL;
    ra.in[1] = Wq; ra.out[1] = wq; ra.n[1] = D_MODEL * D_MODEL;
    ra.in[2] = Wk; ra.out[2] = wk; ra.n[2] = D_MODEL * D_MODEL;
    ra.in[3] = Wv; ra.out[3] = wv; ra.n[3] = D_MODEL * D_MODEL;
    ra.in[4] = Wo; ra.out[4] = wo; ra.n[4] = D_MODEL * D_MODEL;
    ra.in[5] = W1; ra.out[5] = w1; ra.n[5] = D_MODEL * D_FF;
    ra.in[6] = W2; ra.out[6] = w2; ra.n[6] = D_FF * D_MODEL;
    round7_kernel<<<dim3((ROWS * D_MODEL) / 1024, 7), 256>>>(ra);

    const int smem_gemm  = 3 * (128 * 36 + 32 * 136) * 4;      // 107520
    const int smem_smctx = (2 * 128 * 36 + 2 * 32 * 72) * 4;   // 55296

    cudaFuncSetAttribute(gemm_cp_kernel<128, 128, 32, false, false>,
                         cudaFuncAttributeMaxDynamicSharedMemorySize, smem_gemm);
    cudaFuncSetAttribute(gemm_cp_kernel<128, 128, 32, true, true>,
                         cudaFuncAttributeMaxDynamicSharedMemorySize, smem_gemm);
    cudaFuncSetAttribute(qkv_cp_kernel,
                         cudaFuncAttributeMaxDynamicSharedMemorySize, smem_gemm);
    cudaFuncSetAttribute(smctx_tf32_kernel<128, 64, 32>,
                         cudaFuncAttributeMaxDynamicSharedMemorySize, smem_smctx);

    // QKV (outputs rounded)
    qkv_cp_kernel<<<dim3(D_MODEL / 128, ROWS / 128, 3), 256, smem_gemm>>>(
        xr, wq, bq, wk, bk, wv, bv, q, k, v);

    // Scores -> e + partial sums
    scores_tf32_kernel<128, 128, 32><<<dim3(NBX, SEQ / 128, NZ), 256>>>(
        q, k, mask, attn);

    // Softmax + context (ctx rounded)
    smctx_tf32_kernel<128, 64, 32><<<dim3(1, SEQ / 128, NZ), 256, smem_smctx>>>(
        attn, v, ctx);

    // Wo + LN1 (ao exact + rounded copy)
    dim3 g768(D_MODEL / 128, ROWS / 128);
    gemm_cp_kernel<128, 128, 32, false, false><<<g768, 256, smem_gemm>>>(
        ctx, D_MODEL, wo, D_MODEL, t1, D_MODEL, bo, D_MODEL);
    ln_kernel<<<ROWS, 256>>>(t1, X, ln1g, ln1b, ao, aor);

    // FFN
    gemm_cp_kernel<128, 128, 32, true, true><<<dim3(D_FF / 128, ROWS / 128), 256, smem_gemm>>>(
        aor, D_MODEL, w1, D_FF, ffn, D_FF, b1, D_MODEL);
    gemm_cp_kernel<128, 128, 32, false, false><<<g768, 256, smem_gemm>>>(
        ffn, D_FF, w2, D_MODEL, t2, D_MODEL, b2, D_FF);

    ln_kernel<<<ROWS, 256>>>(t2, ao, ln2g, ln2b, out, nullptr);
}

// round 8
// speedup vs baseline: 2.7857x; 1.0065x over previous
#include <cuda_runtime.h>
#include <math.h>
#include <stdint.h>

#define D_MODEL 768
#define N_HEADS 12
#define D_FF    3072
#define D_KH    64
#define BATCH   2
#define SEQ     2048
#define ROWS    (BATCH * SEQ)
#define OUT_ELEMS ((size_t)ROWS * D_MODEL)
#define NZ (BATCH * N_HEADS)
#define NBX (SEQ / 128)

// Scratch
__device__ float g_q[ROWS * D_MODEL];
__device__ float g_k[ROWS * D_MODEL];
__device__ float g_v[ROWS * D_MODEL];
__device__ float g_ctx[ROWS * D_MODEL];
__device__ float g_t1[ROWS * D_MODEL];
__device__ float g_ao[ROWS * D_MODEL];
__device__ float g_aor[ROWS * D_MODEL];
__device__ float g_ffn[ROWS * D_FF];
__device__ float g_t2[ROWS * D_MODEL];
__device__ float g_part[(size_t)NZ * SEQ * NBX];
// tf32-pre-rounded copies
__device__ float g_xr[ROWS * D_MODEL];
__device__ float g_wq[D_MODEL * D_MODEL];
__device__ float g_wk[D_MODEL * D_MODEL];
__device__ float g_wv[D_MODEL * D_MODEL];
__device__ float g_wo[D_MODEL * D_MODEL];
__device__ float g_w1[D_MODEL * D_FF];
__device__ float g_w2[D_FF * D_MODEL];

// ---------------------------------------------------------------------------
// Helpers
// ---------------------------------------------------------------------------
__device__ __forceinline__ uint32_t f2tf32(float f) {
    uint32_t r;
    asm("cvt.rna.tf32.f32 %0, %1;" : "=r"(r) : "f"(f));
    return r;
}
__device__ __forceinline__ float roundtf(float f) { return __uint_as_float(f2tf32(f)); }

__device__ __forceinline__ void mma_tf32(float* c,
                                         uint32_t a0, uint32_t a1, uint32_t a2, uint32_t a3,
                                         uint32_t b0, uint32_t b1) {
    asm("mma.sync.aligned.m16n8k8.row.col.f32.tf32.tf32.f32 "
        "{%0,%1,%2,%3}, {%4,%5,%6,%7}, {%8,%9}, {%0,%1,%2,%3};"
        : "+f"(c[0]), "+f"(c[1]), "+f"(c[2]), "+f"(c[3])
        : "r"(a0), "r"(a1), "r"(a2), "r"(a3), "r"(b0), "r"(b1));
}

__device__ __forceinline__ void ldsm4(uint32_t& r0, uint32_t& r1, uint32_t& r2, uint32_t& r3,
                                      uint32_t a) {
    asm volatile("ldmatrix.sync.aligned.m8n8.x4.shared.b16 {%0,%1,%2,%3}, [%4];"
                 : "=r"(r0), "=r"(r1), "=r"(r2), "=r"(r3) : "r"(a));
}
__device__ __forceinline__ void ldsm2(uint32_t& r0, uint32_t& r1, uint32_t a) {
    asm volatile("ldmatrix.sync.aligned.m8n8.x2.shared.b16 {%0,%1}, [%2];"
                 : "=r"(r0), "=r"(r1) : "r"(a));
}

__device__ __forceinline__ uint32_t smem_u32(const void* p) {
    return (uint32_t)__cvta_generic_to_shared(p);
}

__device__ __forceinline__ void cpa16(uint32_t s, const float* g) {
    asm volatile("cp.async.cg.shared.global [%0], [%1], 16;" :: "r"(s), "l"(g));
}
#define CP_COMMIT() asm volatile("cp.async.commit_group;")
#define CP_WAIT1()  asm volatile("cp.async.wait_group 1;")

__device__ __forceinline__ float warp_sum(float v) {
#pragma unroll
    for (int o = 16; o; o >>= 1) v += __shfl_xor_sync(0xffffffffu, v, o);
    return v;
}

// ---------------------------------------------------------------------------
// Pre-round kernel: 7 segments, each in[i] -> out[i] rounded to tf32.
// ---------------------------------------------------------------------------
struct RoundArgs {
    const float* in[7];
    float* out[7];
    int n[7];
};
__global__ void __launch_bounds__(256)
round7_kernel(RoundArgs a)
{
    int seg = blockIdx.y;
    int base = (blockIdx.x * 256 + threadIdx.x) * 4;
    if (base >= a.n[seg]) return;
    float4 v = *reinterpret_cast<const float4*>(a.in[seg] + base);
    v.x = roundtf(v.x); v.y = roundtf(v.y);
    v.z = roundtf(v.z); v.w = roundtf(v.w);
    *reinterpret_cast<float4*>(a.out[seg] + base) = v;
}

// ---------------------------------------------------------------------------
// cp.async 3-stage pipelined TF32 GEMM, ldmatrix A-frags.
// C = A[M,K](rm) @ B[K,N](rm) + bias. BM=128 BN=128 BK=32, 256 threads.
// ---------------------------------------------------------------------------
template <int BM, int BN, int BK, bool RELU, bool ROUND>
__device__ __forceinline__ void gemm_cp_body(const float* __restrict__ A, int lda,
                                             const float* __restrict__ B, int ldb,
                                             float* __restrict__ C, int ldc,
                                             const float* __restrict__ bias, int K,
                                             int row0, int col0)
{
    extern __shared__ float smem[];
    constexpr int A_ST = BK + 4, B_ST = BN + 8;
    constexpr int SA_W = BM * A_ST, SB_W = BK * B_ST;
    constexpr int STAGE_W = SA_W + SB_W;
    constexpr int WTM = BM / 2, WTN = BN / 4;
    constexpr int MT = WTM / 16, NT = WTN / 8;
    constexpr int LA = BM * BK / (256 * 4);
    constexpr int LB = BK * BN / (256 * 4);

    const int tid = threadIdx.x, lane = tid & 31, wid = tid >> 5;
    const int wm = wid & 1, wn = wid >> 1;
    const int g = lane >> 2, t = lane & 3;

    A += (size_t)row0 * lda;
    B += col0;

    const uint32_t sbase = smem_u32(smem);
    // ldmatrix lane mapping for A tiles: row = (lane&15), col-half = (lane>>4)*4
    const uint32_t aLaneOff = ((wm * WTM + (lane & 15)) * A_ST + (lane >> 4) * 4) * 4;

    int aar[LA], aac[LA], bbr[LB], bbc[LB];
#pragma unroll
    for (int l = 0; l < LA; l++) {
        int idx = tid + l * 256;
        aar[l] = idx / (BK / 4);
        aac[l] = idx % (BK / 4);
    }
#pragma unroll
    for (int l = 0; l < LB; l++) {
        int idx = tid + l * 256;
        bbr[l] = idx / (BN / 4);
        bbc[l] = idx % (BN / 4);
    }

#define ISSUE(kt, st)                                                          \
    {                                                                          \
        uint32_t sa = sbase + (st) * STAGE_W * 4;                              \
        uint32_t sb = sa + SA_W * 4;                                           \
        _Pragma("unroll")                                                      \
        for (int l = 0; l < LA; l++)                                           \
            cpa16(sa + (aar[l] * A_ST + aac[l] * 4) * 4,                       \
                  &A[(size_t)aar[l] * lda + (kt) * BK + aac[l] * 4]);          \
        _Pragma("unroll")                                                      \
        for (int l = 0; l < LB; l++)                                           \
            cpa16(sb + (bbr[l] * B_ST + bbc[l] * 4) * 4,                       \
                  &B[(size_t)((kt) * BK + bbr[l]) * ldb + bbc[l] * 4]);        \
    }

    float c[MT][NT][4] = {};
    const int nk = K / BK;

    ISSUE(0, 0); CP_COMMIT();
    ISSUE(1, 1); CP_COMMIT();

    for (int kt = 0; kt < nk; kt++) {
        CP_WAIT1();
        __syncthreads();
        if (kt + 2 < nk) ISSUE(kt + 2, (kt + 2) % 3);
        CP_COMMIT();

        const uint32_t aStage = sbase + (kt % 3) * STAGE_W * 4 + aLaneOff;
        const uint32_t* pB = reinterpret_cast<const uint32_t*>(smem) + (kt % 3) * STAGE_W + SA_W;
#pragma unroll
        for (int kk = 0; kk < BK / 8; kk++) {
            uint32_t a[MT][4], b[NT][2];
#pragma unroll
            for (int mt = 0; mt < MT; mt++)
                ldsm4(a[mt][0], a[mt][1], a[mt][2], a[mt][3],
                      aStage + (mt * 16 * A_ST + kk * 8) * 4);
#pragma unroll
            for (int nt = 0; nt < NT; nt++) {
                int cc = wn * WTN + nt * 8 + g;
                b[nt][0] = pB[(kk * 8 + t) * B_ST + cc];
                b[nt][1] = pB[(kk * 8 + t + 4) * B_ST + cc];
            }
#pragma unroll
            for (int mt = 0; mt < MT; mt++)
#pragma unroll
                for (int nt = 0; nt < NT; nt++)
                    mma_tf32(c[mt][nt], a[mt][0], a[mt][1], a[mt][2], a[mt][3],
                             b[nt][0], b[nt][1]);
        }
    }
#undef ISSUE

    C += (size_t)row0 * ldc + col0;
#pragma unroll
    for (int mt = 0; mt < MT; mt++) {
        int r = wm * WTM + mt * 16 + g;
#pragma unroll
        for (int nt = 0; nt < NT; nt++) {
            int cc = wn * WTN + nt * 8 + 2 * t;
            float b0 = bias[col0 + cc], b1 = bias[col0 + cc + 1];
            float v00 = c[mt][nt][0] + b0, v01 = c[mt][nt][1] + b1;
            float v10 = c[mt][nt][2] + b0, v11 = c[mt][nt][3] + b1;
            if (RELU) {
                v00 = fmaxf(v00, 0.f); v01 = fmaxf(v01, 0.f);
                v10 = fmaxf(v10, 0.f); v11 = fmaxf(v11, 0.f);
            }
            if (ROUND) {
                v00 = roundtf(v00); v01 = roundtf(v01);
                v10 = roundtf(v10); v11 = roundtf(v11);
            }
            C[(size_t)r * ldc + cc]           = v00;
            C[(size_t)r * ldc + cc + 1]       = v01;
            C[(size_t)(r + 8) * ldc + cc]     = v10;
            C[(size_t)(r + 8) * ldc + cc + 1] = v11;
        }
    }
}

template <int BM, int BN, int BK, bool RELU, bool ROUND>
__global__ void __launch_bounds__(256)
gemm_cp_kernel(const float* __restrict__ A, int lda,
               const float* __restrict__ B, int ldb,
               float* __restrict__ C, int ldc,
               const float* __restrict__ bias, int K)
{
    gemm_cp_body<BM, BN, BK, RELU, ROUND>(A, lda, B, ldb, C, ldc, bias, K,
                                          blockIdx.y * BM, blockIdx.x * BN);
}

__global__ void __launch_bounds__(256)
qkv_cp_kernel(const float* __restrict__ Xr,
              const float* __restrict__ Wq, const float* __restrict__ bq,
              const float* __restrict__ Wk, const float* __restrict__ bk,
              const float* __restrict__ Wv, const float* __restrict__ bv,
              float* __restrict__ q, float* __restrict__ k, float* __restrict__ v)
{
    const float* W; const float* bias; float* C;
    if (blockIdx.z == 0)      { W = Wq; bias = bq; C = q; }
    else if (blockIdx.z == 1) { W = Wk; bias = bk; C = k; }
    else                      { W = Wv; bias = bv; C = v; }
    gemm_cp_body<128, 128, 32, false, true>(Xr, D_MODEL, W, D_MODEL, C, D_MODEL, bias,
                                            D_MODEL, blockIdx.y * 128, blockIdx.x * 128);
}

// ---------------------------------------------------------------------------
// Scores: q/k pre-rounded; writes e = exp(mask(QK/8)) + partial row sums.
// ldmatrix for both A (Q) and B (K, stored [n][k]).
// ---------------------------------------------------------------------------
template <int BM, int BN, int BK>
__global__ void __launch_bounds__(256)
scores_tf32_kernel(const float* __restrict__ Qm, const float* __restrict__ Km,
                   const unsigned char* __restrict__ mask, float* __restrict__ attn)
{
    constexpr int A_ST = BK + 4;
    constexpr int WTM = BM / 2, WTN = BN / 4;
    constexpr int MT = WTM / 16, NT = WTN / 8;
    __shared__ __align__(16) float As[BM][A_ST];
    __shared__ __align__(16) float Bs[BN][A_ST];
    __shared__ float sred[4][BM];

    const int z = blockIdx.z;
    const int b = z / N_HEADS;
    const int h = z % N_HEADS;
    const int tid = threadIdx.x, lane = tid & 31, wid = tid >> 5;
    const int wm = wid & 1, wn = wid >> 1;
    const int g = lane >> 2, t = lane & 3;

    const float* A  = Qm + (size_t)b * SEQ * D_MODEL + h * D_KH + (size_t)blockIdx.y * BM * D_MODEL;
    const float* Bp = Km + (size_t)b * SEQ * D_MODEL + h * D_KH + (size_t)blockIdx.x * BN * D_MODEL;
    float* C = attn + (size_t)z * SEQ * SEQ + (size_t)blockIdx.y * BM * SEQ + (size_t)blockIdx.x * BN;
    const unsigned char* Mp = mask + (size_t)b * SEQ * SEQ + (size_t)blockIdx.y * BM * SEQ + (size_t)blockIdx.x * BN;

    const uint32_t aBase = smem_u32(&As[0][0]) +
        ((wm * WTM + (lane & 15)) * A_ST + (lane >> 4) * 4) * 4;
    const uint32_t bBase = smem_u32(&Bs[0][0]) +
        ((wn * WTN + (lane & 7)) * A_ST + ((lane >> 3) & 1) * 4) * 4;

    float c[MT][NT][4] = {};

    for (int kt = 0; kt < D_KH; kt += BK) {
#pragma unroll
        for (int l = 0; l < BM * BK / (256 * 4); l++) {
            int idx = tid + l * 256;
            int ar = idx / (BK / 4), ac = idx % (BK / 4);
            *reinterpret_cast<float4*>(&As[ar][ac * 4]) =
                *reinterpret_cast<const float4*>(&A[(size_t)ar * D_MODEL + kt + ac * 4]);
        }
#pragma unroll
        for (int l = 0; l < BN * BK / (256 * 4); l++) {
            int idx = tid + l * 256;
            int br = idx / (BK / 4), bc = idx % (BK / 4);
            *reinterpret_cast<float4*>(&Bs[br][bc * 4]) =
                *reinterpret_cast<const float4*>(&Bp[(size_t)br * D_MODEL + kt + bc * 4]);
        }
        __syncthreads();
#pragma unroll
        for (int kk = 0; kk < BK / 8; kk++) {
            uint32_t a[MT][4], bfr[NT][2];
#pragma unroll
            for (int mt = 0; mt < MT; mt++)
                ldsm4(a[mt][0], a[mt][1], a[mt][2], a[mt][3],
                      aBase + (mt * 16 * A_ST + kk * 8) * 4);
#pragma unroll
            for (int nt = 0; nt < NT; nt++)
                ldsm2(bfr[nt][0], bfr[nt][1],
                      bBase + (nt * 8 * A_ST + kk * 8) * 4);
#pragma unroll
            for (int mt = 0; mt < MT; mt++)
#pragma unroll
                for (int nt = 0; nt < NT; nt++)
                    mma_tf32(c[mt][nt], a[mt][0], a[mt][1], a[mt][2], a[mt][3],
                             bfr[nt][0], bfr[nt][1]);
        }
        __syncthreads();
    }

#pragma unroll
    for (int mt = 0; mt < MT; mt++) {
        int r = wm * WTM + mt * 16 + g;
        float s0 = 0.f, s1 = 0.f;
#pragma unroll
        for (int nt = 0; nt < NT; nt++) {
            int cc = wn * WTN + nt * 8 + 2 * t;
            float e00 = Mp[(size_t)r * SEQ + cc]           ? 0.f : __expf(c[mt][nt][0] * 0.125f);
            float e01 = Mp[(size_t)r * SEQ + cc + 1]       ? 0.f : __expf(c[mt][nt][1] * 0.125f);
            float e10 = Mp[(size_t)(r + 8) * SEQ + cc]     ? 0.f : __expf(c[mt][nt][2] * 0.125f);
            float e11 = Mp[(size_t)(r + 8) * SEQ + cc + 1] ? 0.f : __expf(c[mt][nt][3] * 0.125f);
            C[(size_t)r * SEQ + cc]           = e00;
            C[(size_t)r * SEQ + cc + 1]       = e01;
            C[(size_t)(r + 8) * SEQ + cc]     = e10;
            C[(size_t)(r + 8) * SEQ + cc + 1] = e11;
            s0 += e00 + e01;
            s1 += e10 + e11;
        }
        s0 += __shfl_xor_sync(0xffffffffu, s0, 1);
        s0 += __shfl_xor_sync(0xffffffffu, s0, 2);
        s1 += __shfl_xor_sync(0xffffffffu, s1, 1);
        s1 += __shfl_xor_sync(0xffffffffu, s1, 2);
        if (t == 0) {
            sred[wn][r]     = s0;
            sred[wn][r + 8] = s1;
        }
    }
    __syncthreads();
    if (tid < BM) {
        float s = sred[0][tid] + sred[1][tid] + sred[2][tid] + sred[3][tid];
        g_part[((size_t)z * SEQ + blockIdx.y * BM + tid) * NBX + blockIdx.x] = s;
    }
}

// ---------------------------------------------------------------------------
// Fused softmax + context: ldmatrix A (probs), scalar B (V).
// ---------------------------------------------------------------------------
template <int BM, int BN, int BK>
__global__ void __launch_bounds__(256)
smctx_tf32_kernel(float* __restrict__ attn, const float* __restrict__ Vm,
                  float* __restrict__ C)
{
    extern __shared__ float smemf[];
    constexpr int A_ST = BK + 4, B_ST = BN + 8;
    constexpr int WTM = BM / 2, WTN = BN / 4;
    constexpr int MT = WTM / 16, NT = WTN / 8;
    constexpr int LA = BM * BK / (256 * 4);
    constexpr int LB = BK * BN / (256 * 4);
    uint32_t* sA = reinterpret_cast<uint32_t*>(smemf);
    float*    sB = smemf + 2 * BM * A_ST;
    __shared__ float sinv[BM];

    const int z = blockIdx.z;
    const int b = z / N_HEADS;
    const int h = z % N_HEADS;
    const int tid = threadIdx.x, lane = tid & 31, wid = tid >> 5;
    const int wm = wid & 1, wn = wid >> 1;
    const int g = lane >> 2, t = lane & 3;

    float* Araw = attn + (size_t)z * SEQ * SEQ + (size_t)blockIdx.y * BM * SEQ;
    const float* Bp = Vm + (size_t)b * SEQ * D_MODEL + h * D_KH;
    float* Cp = C + (size_t)b * SEQ * D_MODEL + h * D_KH + (size_t)blockIdx.y * BM * D_MODEL;

    const uint32_t aLaneOff = smem_u32(smemf) +
        ((wm * WTM + (lane & 15)) * A_ST + (lane >> 4) * 4) * 4;

    if (tid < BM) {
        const float* pp = &g_part[((size_t)z * SEQ + blockIdx.y * BM + tid) * NBX];
        float s = 0.f;
#pragma unroll
        for (int i = 0; i < NBX; i++) s += pp[i];
        sinv[tid] = 1.0f / s;
    }
    __syncthreads();

    float4 ra[LA], rb[LB];

#define SLOADG(kt)                                                             \
    {                                                                          \
        _Pragma("unroll")                                                      \
        for (int l = 0; l < LA; l++) {                                         \
            int idx = tid + l * 256;                                           \
            int ar = idx / (BK / 4), ac = idx % (BK / 4);                      \
            ra[l] = *reinterpret_cast<const float4*>(                          \
                &Araw[(size_t)ar * SEQ + (kt) * BK + ac * 4]);                 \
        }                                                                      \
        _Pragma("unroll")                                                      \
        for (int l = 0; l < LB; l++) {                                         \
            int idx = tid + l * 256;                                           \
            int br = idx / (BN / 4), bc = idx % (BN / 4);                      \
            rb[l] = *reinterpret_cast<const float4*>(                          \
                &Bp[(size_t)((kt) * BK + br) * D_MODEL + bc * 4]);             \
        }                                                                      \
    }

#define SSTORES(st, kt)                                                        \
    {                                                                          \
        uint32_t* pA = sA + (st) * BM * A_ST;                                  \
        float*    pB = sB + (st) * BK * B_ST;                                  \
        _Pragma("unroll")                                                      \
        for (int l = 0; l < LA; l++) {                                         \
            int idx = tid + l * 256;                                           \
            int ar = idx / (BK / 4), ac = idx % (BK / 4);                      \
            float inv = sinv[ar];                                              \
            float4 p;                                                          \
            p.x = ra[l].x * inv; p.y = ra[l].y * inv;                          \
            p.z = ra[l].z * inv; p.w = ra[l].w * inv;                          \
            pA[ar * A_ST + ac * 4 + 0] = f2tf32(p.x);                          \
            pA[ar * A_ST + ac * 4 + 1] = f2tf32(p.y);                          \
            pA[ar * A_ST + ac * 4 + 2] = f2tf32(p.z);                          \
            pA[ar * A_ST + ac * 4 + 3] = f2tf32(p.w);                          \
            *reinterpret_cast<float4*>(                                        \
                &Araw[(size_t)ar * SEQ + (kt) * BK + ac * 4]) = p;             \
        }                                                                      \
        _Pragma("unroll")                                                      \
        for (int l = 0; l < LB; l++) {                                         \
            int idx = tid + l * 256;                                           \
            int br = idx / (BN / 4), bc = idx % (BN / 4);                      \
            *reinterpret_cast<float4*>(&pB[br * B_ST + bc * 4]) = rb[l];       \
        }                                                                      \
    }

    float c[MT][NT][4] = {};
    const int nk = SEQ / BK;

    SLOADG(0);
    SSTORES(0, 0);

    for (int kt = 1; kt <= nk; kt++) {
        __syncthreads();
        if (kt < nk) SLOADG(kt);
        const uint32_t aStage = aLaneOff + ((kt - 1) & 1) * BM * A_ST * 4;
        const uint32_t* pB = reinterpret_cast<const uint32_t*>(sB + ((kt - 1) & 1) * BK * B_ST);
#pragma unroll
        for (int kk = 0; kk < BK / 8; kk++) {
            uint32_t a[MT][4], bfr[NT][2];
#pragma unroll
            for (int mt = 0; mt < MT; mt++)
                ldsm4(a[mt][0], a[mt][1], a[mt][2], a[mt][3],
                      aStage + (mt * 16 * A_ST + kk * 8) * 4);
#pragma unroll
            for (int nt = 0; nt < NT; nt++) {
                int cc = wn * WTN + nt * 8 + g;
                bfr[nt][0] = pB[(kk * 8 + t) * B_ST + cc];
                bfr[nt][1] = pB[(kk * 8 + t + 4) * B_ST + cc];
            }
#pragma unroll
            for (int mt = 0; mt < MT; mt++)
#pragma unroll
                for (int nt = 0; nt < NT; nt++)
                    mma_tf32(c[mt][nt], a[mt][0], a[mt][1], a[mt][2], a[mt][3],
                             bfr[nt][0], bfr[nt][1]);
        }
        if (kt < nk) SSTORES(kt & 1, kt);
    }
#undef SLOADG
#undef SSTORES

#pragma unroll
    for (int mt = 0; mt < MT; mt++) {
        int r = wm * WTM + mt * 16 + g;
#pragma unroll
        for (int nt = 0; nt < NT; nt++) {
            int cc = wn * WTN + nt * 8 + 2 * t;
            Cp[(size_t)r * D_MODEL + cc]           = roundtf(c[mt][nt][0]);
            Cp[(size_t)r * D_MODEL + cc + 1]       = roundtf(c[mt][nt][1]);
            Cp[(size_t)(r + 8) * D_MODEL + cc]     = roundtf(c[mt][nt][2]);
            Cp[(size_t)(r + 8) * D_MODEL + cc + 1] = roundtf(c[mt][nt][3]);
        }
    }
}

// ---------------------------------------------------------------------------
// LayerNorm: out = LN(x + resid); optional tf32-rounded second output.
// ---------------------------------------------------------------------------
__global__ void __launch_bounds__(256)
ln_kernel(const float* __restrict__ x, const float* __restrict__ resid,
          const float* __restrict__ gamma, const float* __restrict__ beta,
          float* __restrict__ out, float* __restrict__ out_r)
{
    __shared__ float s_s[8];
    __shared__ float s_ss[8];
    const int row = blockIdx.x;
    const int tid = threadIdx.x;
    const int lane = tid & 31;
    const int wid = tid >> 5;
    const float* xr = x + (size_t)row * D_MODEL;
    const float* rr = resid + (size_t)row * D_MODEL;

    float v[3];
    float s = 0.f, ss = 0.f;
#pragma unroll
    for (int i = 0; i < 3; i++) {
        int c = tid + i * 256;
        v[i] = xr[c] + rr[c];
        s  += v[i];
        ss += v[i] * v[i];
    }
    s = warp_sum(s);
    ss = warp_sum(ss);
    if (lane == 0) { s_s[wid] = s; s_ss[wid] = ss; }
    __syncthreads();
    float ts = 0.f, tss = 0.f;
#pragma unroll
    for (int i = 0; i < 8; i++) { ts += s_s[i]; tss += s_ss[i]; }
    const float mean = ts * (1.0f / D_MODEL);
    const float var  = tss * (1.0f / D_MODEL) - mean * mean;
    const float inv  = rsqrtf(var + 1e-5f);

#pragma unroll
    for (int i = 0; i < 3; i++) {
        int c = tid + i * 256;
        float o = (v[i] - mean) * inv * gamma[c] + beta[c];
        out[(size_t)row * D_MODEL + c] = o;
        if (out_r) out_r[(size_t)row * D_MODEL + c] = roundtf(o);
    }
}

// ---------------------------------------------------------------------------
// Launch
// ---------------------------------------------------------------------------
extern "C" void kernel_launch(void* const* d_in, const int* in_sizes, int n_in,
                              void* d_out, int out_size)
{
    const float* X              = (const float*)d_in[0];
    const unsigned char* mask   = (const unsigned char*)d_in[1];
    const float* Wq = (const float*)d_in[2];
    const float* bq = (const float*)d_in[3];
    const float* Wk = (const float*)d_in[4];
    const float* bk = (const float*)d_in[5];
    const float* Wv = (const float*)d_in[6];
    const float* bv = (const float*)d_in[7];
    const float* Wo = (const float*)d_in[8];
    const float* bo = (const float*)d_in[9];
    const float* ln1g = (const float*)d_in[10];
    const float* ln1b = (const float*)d_in[11];
    const float* W1 = (const float*)d_in[12];
    const float* b1 = (const float*)d_in[13];
    const float* W2 = (const float*)d_in[14];
    const float* b2 = (const float*)d_in[15];
    const float* ln2g = (const float*)d_in[16];
    const float* ln2b = (const float*)d_in[17];

    float* out  = (float*)d_out;
    float* attn = out + OUT_ELEMS;

    float *q, *k, *v, *ctx, *t1, *ao, *aor, *ffn, *t2;
    float *xr, *wq, *wk, *wv, *wo, *w1, *w2;
    cudaGetSymbolAddress((void**)&q,   g_q);
    cudaGetSymbolAddress((void**)&k,   g_k);
    cudaGetSymbolAddress((void**)&v,   g_v);
    cudaGetSymbolAddress((void**)&ctx, g_ctx);
    cudaGetSymbolAddress((void**)&t1,  g_t1);
    cudaGetSymbolAddress((void**)&ao,  g_ao);
    cudaGetSymbolAddress((void**)&aor, g_aor);
    cudaGetSymbolAddress((void**)&ffn, g_ffn);
    cudaGetSymbolAddress((void**)&t2,  g_t2);
    cudaGetSymbolAddress((void**)&xr,  g_xr);
    cudaGetSymbolAddress((void**)&wq,  g_wq);
    cudaGetSymbolAddress((void**)&wk,  g_wk);
    cudaGetSymbolAddress((void**)&wv,  g_wv);
    cudaGetSymbolAddress((void**)&wo,  g_wo);
    cudaGetSymbolAddress((void**)&w1,  g_w1);
    cudaGetSymbolAddress((void**)&w2,  g_w2);

    // Pre-round inputs/weights to tf32
    RoundArgs ra;
    ra.in[0] = X;  ra.out[0] = xr; ra.n[0] = ROWS * D_MODEL;
    ra.in[1] = Wq; ra.out[1] = wq; ra.n[1] = D_MODEL * D_MODEL;
    ra.in[2] = Wk; ra.out[2] = wk; ra.n[2] = D_MODEL * D_MODEL;
    ra.in[3] = Wv; ra.out[3] = wv; ra.n[3] = D_MODEL * D_MODEL;
    ra.in[4] = Wo; ra.out[4] = wo; ra.n[4] = D_MODEL * D_MODEL;
    ra.in[5] = W1; ra.out[5] = w1; ra.n[5] = D_MODEL * D_FF;
    ra.in[6] = W2; ra.out[6] = w2; ra.n[6] = D_FF * D_MODEL;
    round7_kernel<<<dim3((ROWS * D_MODEL) / 1024, 7), 256>>>(ra);

    const int smem_gemm  = 3 * (128 * 36 + 32 * 136) * 4;      // 107520
    const int smem_smctx = (2 * 128 * 36 + 2 * 32 * 72) * 4;   // 55296

    cudaFuncSetAttribute(gemm_cp_kernel<128, 128, 32, false, false>,
                         cudaFuncAttributeMaxDynamicSharedMemorySize, smem_gemm);
    cudaFuncSetAttribute(gemm_cp_kernel<128, 128, 32, true, true>,
                         cudaFuncAttributeMaxDynamicSharedMemorySize, smem_gemm);
    cudaFuncSetAttribute(qkv_cp_kernel,
                         cudaFuncAttributeMaxDynamicSharedMemorySize, smem_gemm);
    cudaFuncSetAttribute(smctx_tf32_kernel<128, 64, 32>,
                         cudaFuncAttributeMaxDynamicSharedMemorySize, smem_smctx);

    // QKV (outputs rounded)
    qkv_cp_kernel<<<dim3(D_MODEL / 128, ROWS / 128, 3), 256, smem_gemm>>>(
        xr, wq, bq, wk, bk, wv, bv, q, k, v);

    // Scores -> e + partial sums
    scores_tf32_kernel<128, 128, 32><<<dim3(NBX, SEQ / 128, NZ), 256>>>(
        q, k, mask, attn);

    // Softmax + context (ctx rounded)
    smctx_tf32_kernel<128, 64, 32><<<dim3(1, SEQ / 128, NZ), 256, smem_smctx>>>(
        attn, v, ctx);

    // Wo + LN1 (ao exact + rounded copy)
    dim3 g768(D_MODEL / 128, ROWS / 128);
    gemm_cp_kernel<128, 128, 32, false, false><<<g768, 256, smem_gemm>>>(
        ctx, D_MODEL, wo, D_MODEL, t1, D_MODEL, bo, D_MODEL);
    ln_kernel<<<ROWS, 256>>>(t1, X, ln1g, ln1b, ao, aor);

    // FFN
    gemm_cp_kernel<128, 128, 32, true, true><<<dim3(D_FF / 128, ROWS / 128), 256, smem_gemm>>>(
        aor, D_MODEL, w1, D_FF, ffn, D_FF, b1, D_MODEL);
    gemm_cp_kernel<128, 128, 32, false, false><<<g768, 256, smem_gemm>>>(
        ffn, D_FF, w2, D_MODEL, t2, D_MODEL, b2, D_FF);

    ln_kernel<<<ROWS, 256>>>(t2, ao, ln2g, ln2b, out, nullptr);
}